// round 1
// baseline (speedup 1.0000x reference)
#include <cuda_runtime.h>
#include <math.h>

#define NB 16
#define NP 8192
#define NG 512
#define NM 32
#define ENC 384
#define EPSF 1e-5f

// ---------------- scratch (static device arrays; no allocs) ----------------
__device__ float g_centers[NB * NG * 3];
__device__ float g_nbhd[NB * NG * NM * 3];
__device__ float g_F2[(size_t)NB * NG * NM * 256];   // 256 MB
__device__ float g_FG[NB * NG * 256];
__device__ float g_Htop[NB * NG * 512];
__device__ float g_F3[(size_t)NB * NG * NM * 512];   // 512 MB

// ============================ FPS =============================
// one block per batch, 1024 threads, 8 points per thread (registers)
__global__ void fps_kernel(const float* __restrict__ pts) {
    const int b = blockIdx.x;
    const float* p = pts + (size_t)b * NP * 3;
    const int tid = threadIdx.x;

    float px[8], py[8], pz[8], dd[8];
#pragma unroll
    for (int i = 0; i < 8; i++) {
        int idx = tid + i * 1024;
        px[i] = p[idx * 3 + 0];
        py[i] = p[idx * 3 + 1];
        pz[i] = p[idx * 3 + 2];
        dd[i] = 1e10f;
    }

    __shared__ int sFar;
    __shared__ float swv[32];
    __shared__ int swi[32];
    if (tid == 0) sFar = 0;
    __syncthreads();

    for (int s = 0; s < NG; s++) {
        int far = sFar;
        float cx = p[far * 3 + 0];
        float cy = p[far * 3 + 1];
        float cz = p[far * 3 + 2];
        if (tid == 0) {
            g_centers[(b * NG + s) * 3 + 0] = cx;
            g_centers[(b * NG + s) * 3 + 1] = cy;
            g_centers[(b * NG + s) * 3 + 2] = cz;
        }
        float bv = -1.0f;
        int bi = 0;
#pragma unroll
        for (int i = 0; i < 8; i++) {
            float dx = __fsub_rn(px[i], cx);
            float dy = __fsub_rn(py[i], cy);
            float dz = __fsub_rn(pz[i], cz);
            float d = __fadd_rn(__fadd_rn(__fmul_rn(dx, dx), __fmul_rn(dy, dy)),
                                __fmul_rn(dz, dz));
            dd[i] = fminf(dd[i], d);
            if (dd[i] > bv) { bv = dd[i]; bi = tid + i * 1024; }
        }
        // warp argmax, tie -> smaller index
#pragma unroll
        for (int off = 16; off > 0; off >>= 1) {
            float ov = __shfl_down_sync(0xffffffffu, bv, off);
            int oi = __shfl_down_sync(0xffffffffu, bi, off);
            if (ov > bv || (ov == bv && oi < bi)) { bv = ov; bi = oi; }
        }
        if ((tid & 31) == 0) { swv[tid >> 5] = bv; swi[tid >> 5] = bi; }
        __syncthreads();
        if (tid == 0) {
            float mb = swv[0]; int mi = swi[0];
            for (int w = 1; w < 32; w++) {
                if (swv[w] > mb || (swv[w] == mb && swi[w] < mi)) { mb = swv[w]; mi = swi[w]; }
            }
            sFar = mi;
        }
        __syncthreads();
    }
}

// ============================ kNN =============================
// one block per group, 256 threads, 32 points per thread in registers
__global__ void knn_kernel(const float* __restrict__ pts) {
    const int g = blockIdx.x;           // 0..8191, b-major
    const int b = g >> 9;
    const float* p = pts + (size_t)b * NP * 3;
    const int tid = threadIdx.x;

    const float cx = g_centers[g * 3 + 0];
    const float cy = g_centers[g * 3 + 1];
    const float cz = g_centers[g * 3 + 2];

    float dd[32];
#pragma unroll
    for (int j = 0; j < 32; j++) {
        int idx = tid + j * 256;
        float dx = __fsub_rn(cx, p[idx * 3 + 0]);
        float dy = __fsub_rn(cy, p[idx * 3 + 1]);
        float dz = __fsub_rn(cz, p[idx * 3 + 2]);
        dd[j] = __fadd_rn(__fadd_rn(__fmul_rn(dx, dx), __fmul_rn(dy, dy)),
                          __fmul_rn(dz, dz));
    }

    unsigned mask = 0u;
    __shared__ float swv[8];
    __shared__ int swi[8];
    __shared__ int ssel;
    __shared__ int sel[32];

    for (int it = 0; it < 32; it++) {
        float bv = 3.0e38f;
        int bi = 0x7fffffff;
#pragma unroll
        for (int j = 0; j < 32; j++) {
            if (!((mask >> j) & 1u)) {
                float v = dd[j];
                int pi = tid + j * 256;
                if (v < bv || (v == bv && pi < bi)) { bv = v; bi = pi; }
            }
        }
#pragma unroll
        for (int off = 16; off > 0; off >>= 1) {
            float ov = __shfl_down_sync(0xffffffffu, bv, off);
            int oi = __shfl_down_sync(0xffffffffu, bi, off);
            if (ov < bv || (ov == bv && oi < bi)) { bv = ov; bi = oi; }
        }
        if ((tid & 31) == 0) { swv[tid >> 5] = bv; swi[tid >> 5] = bi; }
        __syncthreads();
        if (tid == 0) {
            float mb = swv[0]; int mi = swi[0];
            for (int w = 1; w < 8; w++) {
                if (swv[w] < mb || (swv[w] == mb && swi[w] < mi)) { mb = swv[w]; mi = swi[w]; }
            }
            ssel = mi;
            sel[it] = mi;
        }
        __syncthreads();
        int w = ssel;
        if ((w & 255) == tid) mask |= (1u << (w >> 8));
    }

    if (tid < 32) {
        int pi = sel[tid];
        g_nbhd[((size_t)g * 32 + tid) * 3 + 0] = p[pi * 3 + 0] - cx;
        g_nbhd[((size_t)g * 32 + tid) * 3 + 1] = p[pi * 3 + 1] - cy;
        g_nbhd[((size_t)g * 32 + tid) * 3 + 2] = p[pi * 3 + 2] - cz;
    }
}

// ===================== E1: f1 (3->128, bn+relu) + f2 (128->256) + group max =====================
// one block per group, 128 threads
__global__ void e1_kernel(const float* __restrict__ W1, const float* __restrict__ b1,
                          const float* __restrict__ g1, const float* __restrict__ be1,
                          const float* __restrict__ m1, const float* __restrict__ v1,
                          const float* __restrict__ W2, const float* __restrict__ b2) {
    const int g = blockIdx.x;
    const int tid = threadIdx.x;

    __shared__ __align__(16) float nb[96];
    __shared__ __align__(16) float f1t[128 * 36];  // [col][row], pad 36
    __shared__ __align__(16) float W2s[16 * 256];
    __shared__ __align__(16) float fgp[4 * 256];

    if (tid < 96) nb[tid] = g_nbhd[(size_t)g * 96 + tid];
    __syncthreads();

    // f1: thread = column c
    {
        const int c = tid;
        float w0 = W1[c], w1 = W1[128 + c], w2 = W1[256 + c];
        float bb = b1[c];
        float sc = g1[c] * rsqrtf(v1[c] + EPSF);
        float mm = m1[c], be = be1[c];
#pragma unroll 8
        for (int r = 0; r < 32; r++) {
            float pre = fmaf(nb[r * 3 + 2], w2, fmaf(nb[r * 3 + 1], w1, fmaf(nb[r * 3 + 0], w0, bb)));
            f1t[c * 36 + r] = fmaxf((pre - mm) * sc + be, 0.0f);
        }
    }
    __syncthreads();

    // f2: rg = rows (8), cg = cols (8)
    const int rg = tid >> 5;   // 0..3 -> rows rg*8..+7
    const int cg = tid & 31;   // cols cg*8..+7
    float acc[8][8];
#pragma unroll
    for (int i = 0; i < 8; i++)
#pragma unroll
        for (int j = 0; j < 8; j++) acc[i][j] = 0.0f;

    for (int kt = 0; kt < 8; kt++) {
        for (int i = tid; i < 1024; i += 128)
            ((float4*)W2s)[i] = ((const float4*)(W2 + kt * 4096))[i];
        __syncthreads();
#pragma unroll
        for (int kk = 0; kk < 16; kk++) {
            int k = kt * 16 + kk;
            float4 fa = *(const float4*)&f1t[k * 36 + rg * 8];
            float4 fb = *(const float4*)&f1t[k * 36 + rg * 8 + 4];
            float4 wa = *(const float4*)&W2s[kk * 256 + cg * 8];
            float4 wb = *(const float4*)&W2s[kk * 256 + cg * 8 + 4];
            float fv[8] = {fa.x, fa.y, fa.z, fa.w, fb.x, fb.y, fb.z, fb.w};
            float wv[8] = {wa.x, wa.y, wa.z, wa.w, wb.x, wb.y, wb.z, wb.w};
#pragma unroll
            for (int i = 0; i < 8; i++)
#pragma unroll
                for (int j = 0; j < 8; j++) acc[i][j] = fmaf(fv[i], wv[j], acc[i][j]);
        }
        __syncthreads();
    }

    // add bias, write F2, partial max
    float pm[8];
#pragma unroll
    for (int j = 0; j < 8; j++) {
        float bj = b2[cg * 8 + j];
#pragma unroll
        for (int i = 0; i < 8; i++) acc[i][j] += bj;
        float m = acc[0][j];
#pragma unroll
        for (int i = 1; i < 8; i++) m = fmaxf(m, acc[i][j]);
        pm[j] = m;
    }
#pragma unroll
    for (int i = 0; i < 8; i++) {
        size_t row = (size_t)g * 32 + rg * 8 + i;
        float4 o0 = {acc[i][0], acc[i][1], acc[i][2], acc[i][3]};
        float4 o1 = {acc[i][4], acc[i][5], acc[i][6], acc[i][7]};
        *(float4*)&g_F2[row * 256 + cg * 8] = o0;
        *(float4*)&g_F2[row * 256 + cg * 8 + 4] = o1;
    }
#pragma unroll
    for (int j = 0; j < 8; j++) fgp[rg * 256 + cg * 8 + j] = pm[j];
    __syncthreads();
    for (int c = tid; c < 256; c += 128) {
        float m = fmaxf(fmaxf(fgp[c], fgp[256 + c]), fmaxf(fgp[512 + c], fgp[768 + c]));
        g_FG[(size_t)g * 256 + c] = m;
    }
}

// ===================== E2: Htop = fg @ W3[0:256] + b3 =====================
__global__ void e2_kernel(const float* __restrict__ W3, const float* __restrict__ b3) {
    const int g = blockIdx.x;
    const int tid = threadIdx.x;  // 128
    __shared__ float fg[256];
    for (int c = tid; c < 256; c += 128) fg[c] = g_FG[(size_t)g * 256 + c];
    __syncthreads();
    float a0 = b3[tid], a1 = b3[tid + 128], a2 = b3[tid + 256], a3 = b3[tid + 384];
    for (int k = 0; k < 256; k++) {
        float v = fg[k];
        const float* w = W3 + k * 512;
        a0 = fmaf(v, w[tid], a0);
        a1 = fmaf(v, w[tid + 128], a1);
        a2 = fmaf(v, w[tid + 256], a2);
        a3 = fmaf(v, w[tid + 384], a3);
    }
    float* h = g_Htop + (size_t)g * 512;
    h[tid] = a0; h[tid + 128] = a1; h[tid + 256] = a2; h[tid + 384] = a3;
}

// ===================== E3a: f3 = relu(bn(Htop + f2 @ W3[256:512])) =====================
// one block per group, 256 threads, dynamic smem
#define E3A_SMEM ((256 * 36 + 16 * 512 + 512) * 4)
__global__ void e3a_kernel(const float* __restrict__ W3,
                           const float* __restrict__ g2, const float* __restrict__ be2,
                           const float* __restrict__ m2, const float* __restrict__ v2) {
    extern __shared__ float sm[];
    float* f2t = sm;                    // [256][36]
    float* W3s = sm + 256 * 36;         // [16][512]
    float* ht = W3s + 16 * 512;         // [512]

    const int g = blockIdx.x;
    const int tid = threadIdx.x;

    for (int idx = tid; idx < 8192; idx += 256) {
        int r = idx >> 8, c = idx & 255;
        f2t[c * 36 + r] = g_F2[(size_t)g * 8192 + idx];
    }
    for (int idx = tid; idx < 512; idx += 256) ht[idx] = g_Htop[(size_t)g * 512 + idx];
    __syncthreads();

    const int rg = tid >> 6;   // 0..3 -> rows rg*8
    const int cg = tid & 63;   // cols cg*8
    float acc[8][8];
#pragma unroll
    for (int i = 0; i < 8; i++)
#pragma unroll
        for (int j = 0; j < 8; j++) acc[i][j] = 0.0f;

    for (int kt = 0; kt < 16; kt++) {
        for (int i = tid; i < 2048; i += 256)
            ((float4*)W3s)[i] = ((const float4*)(W3 + (size_t)(256 + kt * 16) * 512))[i];
        __syncthreads();
#pragma unroll
        for (int kk = 0; kk < 16; kk++) {
            int k = kt * 16 + kk;
            float4 fa = *(const float4*)&f2t[k * 36 + rg * 8];
            float4 fb = *(const float4*)&f2t[k * 36 + rg * 8 + 4];
            float4 wa = *(const float4*)&W3s[kk * 512 + cg * 8];
            float4 wb = *(const float4*)&W3s[kk * 512 + cg * 8 + 4];
            float fv[8] = {fa.x, fa.y, fa.z, fa.w, fb.x, fb.y, fb.z, fb.w};
            float wv[8] = {wa.x, wa.y, wa.z, wa.w, wb.x, wb.y, wb.z, wb.w};
#pragma unroll
            for (int i = 0; i < 8; i++)
#pragma unroll
                for (int j = 0; j < 8; j++) acc[i][j] = fmaf(fv[i], wv[j], acc[i][j]);
        }
        __syncthreads();
    }

#pragma unroll
    for (int j = 0; j < 8; j++) {
        int c = cg * 8 + j;
        float hv = ht[c];
        float sc = g2[c] * rsqrtf(v2[c] + EPSF);
        float mm = m2[c], be = be2[c];
#pragma unroll
        for (int i = 0; i < 8; i++) {
            float pre = acc[i][j] + hv;
            acc[i][j] = fmaxf((pre - mm) * sc + be, 0.0f);
        }
    }
#pragma unroll
    for (int i = 0; i < 8; i++) {
        size_t row = (size_t)g * 32 + rg * 8 + i;
        float4 o0 = {acc[i][0], acc[i][1], acc[i][2], acc[i][3]};
        float4 o1 = {acc[i][4], acc[i][5], acc[i][6], acc[i][7]};
        *(float4*)&g_F3[row * 512 + cg * 8] = o0;
        *(float4*)&g_F3[row * 512 + cg * 8 + 4] = o1;
    }
}

// ===================== E3b: x = max_m (f3 @ W4 + b4) =====================
// one block per group, 256 threads, dynamic smem
#define E3B_SMEM ((512 * 36 + 16 * 384 + 8 * 384) * 4)
__global__ void e3b_kernel(const float* __restrict__ W4, const float* __restrict__ b4,
                           float* __restrict__ out) {
    extern __shared__ float sm[];
    float* f3t = sm;                  // [512][36]
    float* W4s = sm + 512 * 36;       // [16][384]
    float* xp = W4s + 16 * 384;       // [8][384]

    const int g = blockIdx.x;
    const int tid = threadIdx.x;

    for (int idx = tid; idx < 16384; idx += 256) {
        int r = idx >> 9, c = idx & 511;
        f3t[c * 36 + r] = g_F3[(size_t)g * 16384 + idx];
    }
    __syncthreads();

    const int rg = tid >> 5;   // 0..7 -> rows rg*4
    const int cg = tid & 31;   // cols cg*12
    float acc[4][12];
#pragma unroll
    for (int i = 0; i < 4; i++)
#pragma unroll
        for (int j = 0; j < 12; j++) acc[i][j] = 0.0f;

    for (int kt = 0; kt < 32; kt++) {
        __syncthreads();
        for (int i = tid; i < 1536; i += 256)
            ((float4*)W4s)[i] = ((const float4*)(W4 + (size_t)kt * 16 * 384))[i];
        __syncthreads();
#pragma unroll
        for (int kk = 0; kk < 16; kk++) {
            int k = kt * 16 + kk;
            float4 fa = *(const float4*)&f3t[k * 36 + rg * 4];
            float4 w0 = *(const float4*)&W4s[kk * 384 + cg * 12];
            float4 w1 = *(const float4*)&W4s[kk * 384 + cg * 12 + 4];
            float4 w2 = *(const float4*)&W4s[kk * 384 + cg * 12 + 8];
            float fv[4] = {fa.x, fa.y, fa.z, fa.w};
            float wv[12] = {w0.x, w0.y, w0.z, w0.w, w1.x, w1.y, w1.z, w1.w,
                            w2.x, w2.y, w2.z, w2.w};
#pragma unroll
            for (int i = 0; i < 4; i++)
#pragma unroll
                for (int j = 0; j < 12; j++) acc[i][j] = fmaf(fv[i], wv[j], acc[i][j]);
        }
    }
    __syncthreads();
#pragma unroll
    for (int j = 0; j < 12; j++) {
        float m = fmaxf(fmaxf(acc[0][j], acc[1][j]), fmaxf(acc[2][j], acc[3][j]));
        xp[rg * 384 + cg * 12 + j] = m;
    }
    __syncthreads();
    for (int c = tid; c < 384; c += 256) {
        float m = xp[c];
#pragma unroll
        for (int w = 1; w < 8; w++) m = fmaxf(m, xp[w * 384 + c]);
        out[(size_t)g * 384 + c] = m + b4[c];
    }
}

// ===================== pos embed + cls =====================
__global__ void pos_kernel(const float* __restrict__ Wp1, const float* __restrict__ bp1,
                           const float* __restrict__ Wp2, const float* __restrict__ bp2,
                           const float* __restrict__ cls_pos, float* __restrict__ out) {
    const int row = blockIdx.x;   // 0..512
    const int b = blockIdx.y;
    const int tid = threadIdx.x;  // 128
    float* op = out + (size_t)NB * NG * ENC + ((size_t)b * (NG + 1) + row) * ENC;
    if (row == 0) {
        for (int c = tid; c < ENC; c += 128) op[c] = cls_pos[c];
        return;
    }
    const int g = b * NG + row - 1;
    float cx = g_centers[g * 3 + 0], cy = g_centers[g * 3 + 1], cz = g_centers[g * 3 + 2];
    __shared__ float h[128];
    {
        float pre = fmaf(cz, Wp1[256 + tid], fmaf(cy, Wp1[128 + tid], fmaf(cx, Wp1[tid], bp1[tid])));
        float x3 = pre * pre * pre;
        float inner = 0.7978845608028654f * fmaf(0.044715f, x3, pre);
        h[tid] = 0.5f * pre * (1.0f + tanhf(inner));
    }
    __syncthreads();
#pragma unroll
    for (int j = 0; j < 3; j++) {
        int c = tid + 128 * j;
        float a = bp2[c];
        for (int k = 0; k < 128; k++) a = fmaf(h[k], Wp2[k * 384 + c], a);
        op[c] = a;
    }
}

// ============================ launch ============================
extern "C" void kernel_launch(void* const* d_in, const int* in_sizes, int n_in,
                              void* d_out, int out_size) {
    const float* pts = (const float*)d_in[0];
    const float* W1 = (const float*)d_in[1];
    const float* b1 = (const float*)d_in[2];
    const float* g1 = (const float*)d_in[3];
    const float* be1 = (const float*)d_in[4];
    const float* m1 = (const float*)d_in[5];
    const float* v1 = (const float*)d_in[6];
    const float* W2 = (const float*)d_in[7];
    const float* b2 = (const float*)d_in[8];
    const float* W3 = (const float*)d_in[9];
    const float* b3 = (const float*)d_in[10];
    const float* g2 = (const float*)d_in[11];
    const float* be2 = (const float*)d_in[12];
    const float* m2 = (const float*)d_in[13];
    const float* v2 = (const float*)d_in[14];
    const float* W4 = (const float*)d_in[15];
    const float* b4 = (const float*)d_in[16];
    const float* Wp1 = (const float*)d_in[17];
    const float* bp1 = (const float*)d_in[18];
    const float* Wp2 = (const float*)d_in[19];
    const float* bp2 = (const float*)d_in[20];
    const float* cls_pos = (const float*)d_in[21];
    float* out = (float*)d_out;

    cudaFuncSetAttribute(e3a_kernel, cudaFuncAttributeMaxDynamicSharedMemorySize, E3A_SMEM);
    cudaFuncSetAttribute(e3b_kernel, cudaFuncAttributeMaxDynamicSharedMemorySize, E3B_SMEM);

    fps_kernel<<<NB, 1024>>>(pts);
    knn_kernel<<<NB * NG, 256>>>(pts);
    e1_kernel<<<NB * NG, 128>>>(W1, b1, g1, be1, m1, v1, W2, b2);
    e2_kernel<<<NB * NG, 128>>>(W3, b3);
    e3a_kernel<<<NB * NG, 256, E3A_SMEM>>>(W3, g2, be2, m2, v2);
    e3b_kernel<<<NB * NG, 256, E3B_SMEM>>>(W4, b4, out);
    pos_kernel<<<dim3(NG + 1, NB), 128>>>(Wp1, bp1, Wp2, bp2, cls_pos, out);
}

// round 2
// speedup vs baseline: 1.0000x; 1.0000x over previous
#include <cuda_runtime.h>
#include <math.h>

#define NB 16
#define NP 8192
#define NG 512
#define NM 32
#define ENC 384
#define EPSF 1e-5f

// ---------------- scratch (static device arrays; no allocs) ----------------
__device__ float g_centers[NB * NG * 3];
__device__ float g_nbhd[NB * NG * NM * 3];
__device__ float g_F2[(size_t)NB * NG * NM * 256];   // 256 MB
__device__ float g_FG[NB * NG * 256];
__device__ float g_Htop[NB * NG * 512];
__device__ float g_F3[(size_t)NB * NG * NM * 512];   // 512 MB

// ============================ FPS =============================
// one block per batch, 1024 threads, 8 points per thread (registers)
__global__ void fps_kernel(const float* __restrict__ pts) {
    const int b = blockIdx.x;
    const float* p = pts + (size_t)b * NP * 3;
    const int tid = threadIdx.x;

    float px[8], py[8], pz[8], dd[8];
#pragma unroll
    for (int i = 0; i < 8; i++) {
        int idx = tid + i * 1024;
        px[i] = p[idx * 3 + 0];
        py[i] = p[idx * 3 + 1];
        pz[i] = p[idx * 3 + 2];
        dd[i] = 1e10f;
    }

    __shared__ int sFar;
    __shared__ float swv[32];
    __shared__ int swi[32];
    if (tid == 0) sFar = 0;
    __syncthreads();

    for (int s = 0; s < NG; s++) {
        int far = sFar;
        float cx = p[far * 3 + 0];
        float cy = p[far * 3 + 1];
        float cz = p[far * 3 + 2];
        if (tid == 0) {
            g_centers[(b * NG + s) * 3 + 0] = cx;
            g_centers[(b * NG + s) * 3 + 1] = cy;
            g_centers[(b * NG + s) * 3 + 2] = cz;
        }
        float bv = -1.0f;
        int bi = 0;
#pragma unroll
        for (int i = 0; i < 8; i++) {
            float dx = __fsub_rn(px[i], cx);
            float dy = __fsub_rn(py[i], cy);
            float dz = __fsub_rn(pz[i], cz);
            float d = __fadd_rn(__fadd_rn(__fmul_rn(dx, dx), __fmul_rn(dy, dy)),
                                __fmul_rn(dz, dz));
            dd[i] = fminf(dd[i], d);
            if (dd[i] > bv) { bv = dd[i]; bi = tid + i * 1024; }
        }
        // warp argmax, tie -> smaller index
#pragma unroll
        for (int off = 16; off > 0; off >>= 1) {
            float ov = __shfl_down_sync(0xffffffffu, bv, off);
            int oi = __shfl_down_sync(0xffffffffu, bi, off);
            if (ov > bv || (ov == bv && oi < bi)) { bv = ov; bi = oi; }
        }
        if ((tid & 31) == 0) { swv[tid >> 5] = bv; swi[tid >> 5] = bi; }
        __syncthreads();
        if (tid == 0) {
            float mb = swv[0]; int mi = swi[0];
            for (int w = 1; w < 32; w++) {
                if (swv[w] > mb || (swv[w] == mb && swi[w] < mi)) { mb = swv[w]; mi = swi[w]; }
            }
            sFar = mi;
        }
        __syncthreads();
    }
}

// ============================ kNN =============================
// one block per group, 256 threads, 32 points per thread in registers
__global__ void knn_kernel(const float* __restrict__ pts) {
    const int g = blockIdx.x;           // 0..8191, b-major
    const int b = g >> 9;
    const float* p = pts + (size_t)b * NP * 3;
    const int tid = threadIdx.x;

    const float cx = g_centers[g * 3 + 0];
    const float cy = g_centers[g * 3 + 1];
    const float cz = g_centers[g * 3 + 2];

    float dd[32];
#pragma unroll
    for (int j = 0; j < 32; j++) {
        int idx = tid + j * 256;
        float dx = __fsub_rn(cx, p[idx * 3 + 0]);
        float dy = __fsub_rn(cy, p[idx * 3 + 1]);
        float dz = __fsub_rn(cz, p[idx * 3 + 2]);
        dd[j] = __fadd_rn(__fadd_rn(__fmul_rn(dx, dx), __fmul_rn(dy, dy)),
                          __fmul_rn(dz, dz));
    }

    unsigned mask = 0u;
    __shared__ float swv[8];
    __shared__ int swi[8];
    __shared__ int ssel;
    __shared__ int sel[32];

    for (int it = 0; it < 32; it++) {
        float bv = 3.0e38f;
        int bi = 0x7fffffff;
#pragma unroll
        for (int j = 0; j < 32; j++) {
            if (!((mask >> j) & 1u)) {
                float v = dd[j];
                int pi = tid + j * 256;
                if (v < bv || (v == bv && pi < bi)) { bv = v; bi = pi; }
            }
        }
#pragma unroll
        for (int off = 16; off > 0; off >>= 1) {
            float ov = __shfl_down_sync(0xffffffffu, bv, off);
            int oi = __shfl_down_sync(0xffffffffu, bi, off);
            if (ov < bv || (ov == bv && oi < bi)) { bv = ov; bi = oi; }
        }
        if ((tid & 31) == 0) { swv[tid >> 5] = bv; swi[tid >> 5] = bi; }
        __syncthreads();
        if (tid == 0) {
            float mb = swv[0]; int mi = swi[0];
            for (int w = 1; w < 8; w++) {
                if (swv[w] < mb || (swv[w] == mb && swi[w] < mi)) { mb = swv[w]; mi = swi[w]; }
            }
            ssel = mi;
            sel[it] = mi;
        }
        __syncthreads();
        int w = ssel;
        if ((w & 255) == tid) mask |= (1u << (w >> 8));
    }

    if (tid < 32) {
        int pi = sel[tid];
        g_nbhd[((size_t)g * 32 + tid) * 3 + 0] = p[pi * 3 + 0] - cx;
        g_nbhd[((size_t)g * 32 + tid) * 3 + 1] = p[pi * 3 + 1] - cy;
        g_nbhd[((size_t)g * 32 + tid) * 3 + 2] = p[pi * 3 + 2] - cz;
    }
}

// ===================== E1: f1 (3->128, bn+relu) + f2 (128->256) + group max =====================
// one block per group, 128 threads
__global__ void e1_kernel(const float* __restrict__ W1, const float* __restrict__ b1,
                          const float* __restrict__ g1, const float* __restrict__ be1,
                          const float* __restrict__ m1, const float* __restrict__ v1,
                          const float* __restrict__ W2, const float* __restrict__ b2) {
    const int g = blockIdx.x;
    const int tid = threadIdx.x;

    __shared__ __align__(16) float nb[96];
    __shared__ __align__(16) float f1t[128 * 36];  // [col][row], pad 36
    __shared__ __align__(16) float W2s[16 * 256];
    __shared__ __align__(16) float fgp[4 * 256];

    if (tid < 96) nb[tid] = g_nbhd[(size_t)g * 96 + tid];
    __syncthreads();

    // f1: thread = column c
    {
        const int c = tid;
        float w0 = W1[c], w1 = W1[128 + c], w2 = W1[256 + c];
        float bb = b1[c];
        float sc = g1[c] * rsqrtf(v1[c] + EPSF);
        float mm = m1[c], be = be1[c];
#pragma unroll 8
        for (int r = 0; r < 32; r++) {
            float pre = fmaf(nb[r * 3 + 2], w2, fmaf(nb[r * 3 + 1], w1, fmaf(nb[r * 3 + 0], w0, bb)));
            f1t[c * 36 + r] = fmaxf((pre - mm) * sc + be, 0.0f);
        }
    }
    __syncthreads();

    // f2: rg = rows (8), cg = cols (8)
    const int rg = tid >> 5;   // 0..3 -> rows rg*8..+7
    const int cg = tid & 31;   // cols cg*8..+7
    float acc[8][8];
#pragma unroll
    for (int i = 0; i < 8; i++)
#pragma unroll
        for (int j = 0; j < 8; j++) acc[i][j] = 0.0f;

    for (int kt = 0; kt < 8; kt++) {
        for (int i = tid; i < 1024; i += 128)
            ((float4*)W2s)[i] = ((const float4*)(W2 + kt * 4096))[i];
        __syncthreads();
#pragma unroll
        for (int kk = 0; kk < 16; kk++) {
            int k = kt * 16 + kk;
            float4 fa = *(const float4*)&f1t[k * 36 + rg * 8];
            float4 fb = *(const float4*)&f1t[k * 36 + rg * 8 + 4];
            float4 wa = *(const float4*)&W2s[kk * 256 + cg * 8];
            float4 wb = *(const float4*)&W2s[kk * 256 + cg * 8 + 4];
            float fv[8] = {fa.x, fa.y, fa.z, fa.w, fb.x, fb.y, fb.z, fb.w};
            float wv[8] = {wa.x, wa.y, wa.z, wa.w, wb.x, wb.y, wb.z, wb.w};
#pragma unroll
            for (int i = 0; i < 8; i++)
#pragma unroll
                for (int j = 0; j < 8; j++) acc[i][j] = fmaf(fv[i], wv[j], acc[i][j]);
        }
        __syncthreads();
    }

    // add bias, write F2, partial max
    float pm[8];
#pragma unroll
    for (int j = 0; j < 8; j++) {
        float bj = b2[cg * 8 + j];
#pragma unroll
        for (int i = 0; i < 8; i++) acc[i][j] += bj;
        float m = acc[0][j];
#pragma unroll
        for (int i = 1; i < 8; i++) m = fmaxf(m, acc[i][j]);
        pm[j] = m;
    }
#pragma unroll
    for (int i = 0; i < 8; i++) {
        size_t row = (size_t)g * 32 + rg * 8 + i;
        float4 o0 = {acc[i][0], acc[i][1], acc[i][2], acc[i][3]};
        float4 o1 = {acc[i][4], acc[i][5], acc[i][6], acc[i][7]};
        *(float4*)&g_F2[row * 256 + cg * 8] = o0;
        *(float4*)&g_F2[row * 256 + cg * 8 + 4] = o1;
    }
#pragma unroll
    for (int j = 0; j < 8; j++) fgp[rg * 256 + cg * 8 + j] = pm[j];
    __syncthreads();
    for (int c = tid; c < 256; c += 128) {
        float m = fmaxf(fmaxf(fgp[c], fgp[256 + c]), fmaxf(fgp[512 + c], fgp[768 + c]));
        g_FG[(size_t)g * 256 + c] = m;
    }
}

// ===================== E2: Htop = fg @ W3[0:256] + b3 =====================
__global__ void e2_kernel(const float* __restrict__ W3, const float* __restrict__ b3) {
    const int g = blockIdx.x;
    const int tid = threadIdx.x;  // 128
    __shared__ float fg[256];
    for (int c = tid; c < 256; c += 128) fg[c] = g_FG[(size_t)g * 256 + c];
    __syncthreads();
    float a0 = b3[tid], a1 = b3[tid + 128], a2 = b3[tid + 256], a3 = b3[tid + 384];
    for (int k = 0; k < 256; k++) {
        float v = fg[k];
        const float* w = W3 + k * 512;
        a0 = fmaf(v, w[tid], a0);
        a1 = fmaf(v, w[tid + 128], a1);
        a2 = fmaf(v, w[tid + 256], a2);
        a3 = fmaf(v, w[tid + 384], a3);
    }
    float* h = g_Htop + (size_t)g * 512;
    h[tid] = a0; h[tid + 128] = a1; h[tid + 256] = a2; h[tid + 384] = a3;
}

// ===================== E3a: f3 = relu(bn(Htop + f2 @ W3[256:512])) =====================
// one block per group, 256 threads, dynamic smem
#define E3A_SMEM ((256 * 36 + 16 * 512 + 512) * 4)
__global__ void e3a_kernel(const float* __restrict__ W3,
                           const float* __restrict__ g2, const float* __restrict__ be2,
                           const float* __restrict__ m2, const float* __restrict__ v2) {
    extern __shared__ float sm[];
    float* f2t = sm;                    // [256][36]
    float* W3s = sm + 256 * 36;         // [16][512]
    float* ht = W3s + 16 * 512;         // [512]

    const int g = blockIdx.x;
    const int tid = threadIdx.x;

    for (int idx = tid; idx < 8192; idx += 256) {
        int r = idx >> 8, c = idx & 255;
        f2t[c * 36 + r] = g_F2[(size_t)g * 8192 + idx];
    }
    for (int idx = tid; idx < 512; idx += 256) ht[idx] = g_Htop[(size_t)g * 512 + idx];
    __syncthreads();

    const int rg = tid >> 6;   // 0..3 -> rows rg*8
    const int cg = tid & 63;   // cols cg*8
    float acc[8][8];
#pragma unroll
    for (int i = 0; i < 8; i++)
#pragma unroll
        for (int j = 0; j < 8; j++) acc[i][j] = 0.0f;

    for (int kt = 0; kt < 16; kt++) {
        for (int i = tid; i < 2048; i += 256)
            ((float4*)W3s)[i] = ((const float4*)(W3 + (size_t)(256 + kt * 16) * 512))[i];
        __syncthreads();
#pragma unroll
        for (int kk = 0; kk < 16; kk++) {
            int k = kt * 16 + kk;
            float4 fa = *(const float4*)&f2t[k * 36 + rg * 8];
            float4 fb = *(const float4*)&f2t[k * 36 + rg * 8 + 4];
            float4 wa = *(const float4*)&W3s[kk * 512 + cg * 8];
            float4 wb = *(const float4*)&W3s[kk * 512 + cg * 8 + 4];
            float fv[8] = {fa.x, fa.y, fa.z, fa.w, fb.x, fb.y, fb.z, fb.w};
            float wv[8] = {wa.x, wa.y, wa.z, wa.w, wb.x, wb.y, wb.z, wb.w};
#pragma unroll
            for (int i = 0; i < 8; i++)
#pragma unroll
                for (int j = 0; j < 8; j++) acc[i][j] = fmaf(fv[i], wv[j], acc[i][j]);
        }
        __syncthreads();
    }

#pragma unroll
    for (int j = 0; j < 8; j++) {
        int c = cg * 8 + j;
        float hv = ht[c];
        float sc = g2[c] * rsqrtf(v2[c] + EPSF);
        float mm = m2[c], be = be2[c];
#pragma unroll
        for (int i = 0; i < 8; i++) {
            float pre = acc[i][j] + hv;
            acc[i][j] = fmaxf((pre - mm) * sc + be, 0.0f);
        }
    }
#pragma unroll
    for (int i = 0; i < 8; i++) {
        size_t row = (size_t)g * 32 + rg * 8 + i;
        float4 o0 = {acc[i][0], acc[i][1], acc[i][2], acc[i][3]};
        float4 o1 = {acc[i][4], acc[i][5], acc[i][6], acc[i][7]};
        *(float4*)&g_F3[row * 512 + cg * 8] = o0;
        *(float4*)&g_F3[row * 512 + cg * 8 + 4] = o1;
    }
}

// ===================== E3b: x = max_m (f3 @ W4 + b4) =====================
// one block per group, 256 threads, dynamic smem
#define E3B_SMEM ((512 * 36 + 16 * 384 + 8 * 384) * 4)
__global__ void e3b_kernel(const float* __restrict__ W4, const float* __restrict__ b4,
                           float* __restrict__ out) {
    extern __shared__ float sm[];
    float* f3t = sm;                  // [512][36]
    float* W4s = sm + 512 * 36;       // [16][384]
    float* xp = W4s + 16 * 384;       // [8][384]

    const int g = blockIdx.x;
    const int tid = threadIdx.x;

    for (int idx = tid; idx < 16384; idx += 256) {
        int r = idx >> 9, c = idx & 511;
        f3t[c * 36 + r] = g_F3[(size_t)g * 16384 + idx];
    }
    __syncthreads();

    const int rg = tid >> 5;   // 0..7 -> rows rg*4
    const int cg = tid & 31;   // cols cg*12
    float acc[4][12];
#pragma unroll
    for (int i = 0; i < 4; i++)
#pragma unroll
        for (int j = 0; j < 12; j++) acc[i][j] = 0.0f;

    for (int kt = 0; kt < 32; kt++) {
        __syncthreads();
        for (int i = tid; i < 1536; i += 256)
            ((float4*)W4s)[i] = ((const float4*)(W4 + (size_t)kt * 16 * 384))[i];
        __syncthreads();
#pragma unroll
        for (int kk = 0; kk < 16; kk++) {
            int k = kt * 16 + kk;
            float4 fa = *(const float4*)&f3t[k * 36 + rg * 4];
            float4 w0 = *(const float4*)&W4s[kk * 384 + cg * 12];
            float4 w1 = *(const float4*)&W4s[kk * 384 + cg * 12 + 4];
            float4 w2 = *(const float4*)&W4s[kk * 384 + cg * 12 + 8];
            float fv[4] = {fa.x, fa.y, fa.z, fa.w};
            float wv[12] = {w0.x, w0.y, w0.z, w0.w, w1.x, w1.y, w1.z, w1.w,
                            w2.x, w2.y, w2.z, w2.w};
#pragma unroll
            for (int i = 0; i < 4; i++)
#pragma unroll
                for (int j = 0; j < 12; j++) acc[i][j] = fmaf(fv[i], wv[j], acc[i][j]);
        }
    }
    __syncthreads();
#pragma unroll
    for (int j = 0; j < 12; j++) {
        float m = fmaxf(fmaxf(acc[0][j], acc[1][j]), fmaxf(acc[2][j], acc[3][j]));
        xp[rg * 384 + cg * 12 + j] = m;
    }
    __syncthreads();
    for (int c = tid; c < 384; c += 256) {
        float m = xp[c];
#pragma unroll
        for (int w = 1; w < 8; w++) m = fmaxf(m, xp[w * 384 + c]);
        out[(size_t)g * 384 + c] = m + b4[c];
    }
}

// ===================== pos embed + cls =====================
__global__ void pos_kernel(const float* __restrict__ Wp1, const float* __restrict__ bp1,
                           const float* __restrict__ Wp2, const float* __restrict__ bp2,
                           const float* __restrict__ cls_pos, float* __restrict__ out) {
    const int row = blockIdx.x;   // 0..512
    const int b = blockIdx.y;
    const int tid = threadIdx.x;  // 128
    float* op = out + (size_t)NB * NG * ENC + ((size_t)b * (NG + 1) + row) * ENC;
    if (row == 0) {
        for (int c = tid; c < ENC; c += 128) op[c] = cls_pos[c];
        return;
    }
    const int g = b * NG + row - 1;
    float cx = g_centers[g * 3 + 0], cy = g_centers[g * 3 + 1], cz = g_centers[g * 3 + 2];
    __shared__ float h[128];
    {
        float pre = fmaf(cz, Wp1[256 + tid], fmaf(cy, Wp1[128 + tid], fmaf(cx, Wp1[tid], bp1[tid])));
        float x3 = pre * pre * pre;
        float inner = 0.7978845608028654f * fmaf(0.044715f, x3, pre);
        h[tid] = 0.5f * pre * (1.0f + tanhf(inner));
    }
    __syncthreads();
#pragma unroll
    for (int j = 0; j < 3; j++) {
        int c = tid + 128 * j;
        float a = bp2[c];
        for (int k = 0; k < 128; k++) a = fmaf(h[k], Wp2[k * 384 + c], a);
        op[c] = a;
    }
}

// ============================ launch ============================
extern "C" void kernel_launch(void* const* d_in, const int* in_sizes, int n_in,
                              void* d_out, int out_size) {
    const float* pts = (const float*)d_in[0];
    const float* W1 = (const float*)d_in[1];
    const float* b1 = (const float*)d_in[2];
    const float* g1 = (const float*)d_in[3];
    const float* be1 = (const float*)d_in[4];
    const float* m1 = (const float*)d_in[5];
    const float* v1 = (const float*)d_in[6];
    const float* W2 = (const float*)d_in[7];
    const float* b2 = (const float*)d_in[8];
    const float* W3 = (const float*)d_in[9];
    const float* b3 = (const float*)d_in[10];
    const float* g2 = (const float*)d_in[11];
    const float* be2 = (const float*)d_in[12];
    const float* m2 = (const float*)d_in[13];
    const float* v2 = (const float*)d_in[14];
    const float* W4 = (const float*)d_in[15];
    const float* b4 = (const float*)d_in[16];
    const float* Wp1 = (const float*)d_in[17];
    const float* bp1 = (const float*)d_in[18];
    const float* Wp2 = (const float*)d_in[19];
    const float* bp2 = (const float*)d_in[20];
    const float* cls_pos = (const float*)d_in[21];
    float* out = (float*)d_out;

    cudaFuncSetAttribute(e3a_kernel, cudaFuncAttributeMaxDynamicSharedMemorySize, E3A_SMEM);
    cudaFuncSetAttribute(e3b_kernel, cudaFuncAttributeMaxDynamicSharedMemorySize, E3B_SMEM);

    fps_kernel<<<NB, 1024>>>(pts);
    knn_kernel<<<NB * NG, 256>>>(pts);
    e1_kernel<<<NB * NG, 128>>>(W1, b1, g1, be1, m1, v1, W2, b2);
    e2_kernel<<<NB * NG, 128>>>(W3, b3);
    e3a_kernel<<<NB * NG, 256, E3A_SMEM>>>(W3, g2, be2, m2, v2);
    e3b_kernel<<<NB * NG, 256, E3B_SMEM>>>(W4, b4, out);
    pos_kernel<<<dim3(NG + 1, NB), 128>>>(Wp1, bp1, Wp2, bp2, cls_pos, out);
}

// round 4
// speedup vs baseline: 1.2781x; 1.2781x over previous
#include <cuda_runtime.h>
#include <math.h>
#include <stdint.h>

#define NB 16
#define NP 8192
#define NG 512
#define NM 32
#define ENC 384
#define EPSF 1e-5f

// ---------------- scratch ----------------
__device__ float g_centers[NB * NG * 3];
__device__ float g_nbhd[NB * NG * NM * 3];
__device__ float g_F2[(size_t)NB * NG * NM * 256];
__device__ float g_FG[NB * NG * 256];
__device__ float g_Htop[NB * NG * 512];
__device__ float g_F3[(size_t)NB * NG * NM * 512];
__device__ float g_W3T[512 * 512];   // W3^T [n][k], tf32-rounded
__device__ float g_W4T[384 * 512];   // W4^T [n][k], tf32-rounded

__device__ __forceinline__ float tf32_rna(float x) {
    uint32_t u;
    asm("cvt.rna.tf32.f32 %0, %1;" : "=r"(u) : "f"(x));
    return __uint_as_float(u);
}
__device__ __forceinline__ void mma16n8k8(float* c, const uint32_t* a, const uint32_t* b) {
    asm volatile(
        "mma.sync.aligned.m16n8k8.row.col.f32.tf32.tf32.f32 "
        "{%0,%1,%2,%3}, {%4,%5,%6,%7}, {%8,%9}, {%0,%1,%2,%3};"
        : "+f"(c[0]), "+f"(c[1]), "+f"(c[2]), "+f"(c[3])
        : "r"(a[0]), "r"(a[1]), "r"(a[2]), "r"(a[3]), "r"(b[0]), "r"(b[1]));
}

// ============================ FPS =============================
__global__ void fps_kernel(const float* __restrict__ pts) {
    const int b = blockIdx.x;
    const float* p = pts + (size_t)b * NP * 3;
    const int tid = threadIdx.x;

    float px[8], py[8], pz[8], dd[8];
#pragma unroll
    for (int i = 0; i < 8; i++) {
        int idx = tid + i * 1024;
        px[i] = p[idx * 3 + 0];
        py[i] = p[idx * 3 + 1];
        pz[i] = p[idx * 3 + 2];
        dd[i] = 1e10f;
    }
    __shared__ int sFar;
    __shared__ float swv[32];
    __shared__ int swi[32];
    if (tid == 0) sFar = 0;
    __syncthreads();

    for (int s = 0; s < NG; s++) {
        int far = sFar;
        float cx = p[far * 3 + 0];
        float cy = p[far * 3 + 1];
        float cz = p[far * 3 + 2];
        if (tid == 0) {
            g_centers[(b * NG + s) * 3 + 0] = cx;
            g_centers[(b * NG + s) * 3 + 1] = cy;
            g_centers[(b * NG + s) * 3 + 2] = cz;
        }
        float bv = -1.0f;
        int bi = 0;
#pragma unroll
        for (int i = 0; i < 8; i++) {
            float dx = __fsub_rn(px[i], cx);
            float dy = __fsub_rn(py[i], cy);
            float dz = __fsub_rn(pz[i], cz);
            float d = __fadd_rn(__fadd_rn(__fmul_rn(dx, dx), __fmul_rn(dy, dy)),
                                __fmul_rn(dz, dz));
            dd[i] = fminf(dd[i], d);
            if (dd[i] > bv) { bv = dd[i]; bi = tid + i * 1024; }
        }
#pragma unroll
        for (int off = 16; off > 0; off >>= 1) {
            float ov = __shfl_down_sync(0xffffffffu, bv, off);
            int oi = __shfl_down_sync(0xffffffffu, bi, off);
            if (ov > bv || (ov == bv && oi < bi)) { bv = ov; bi = oi; }
        }
        if ((tid & 31) == 0) { swv[tid >> 5] = bv; swi[tid >> 5] = bi; }
        __syncthreads();
        if (tid == 0) {
            float mb = swv[0]; int mi = swi[0];
            for (int w = 1; w < 32; w++) {
                if (swv[w] > mb || (swv[w] == mb && swi[w] < mi)) { mb = swv[w]; mi = swi[w]; }
            }
            sFar = mi;
        }
        __syncthreads();
    }
}

// ============================ kNN =============================
__global__ void knn_kernel(const float* __restrict__ pts) {
    const int g = blockIdx.x;
    const int b = g >> 9;
    const float* p = pts + (size_t)b * NP * 3;
    const int tid = threadIdx.x;

    const float cx = g_centers[g * 3 + 0];
    const float cy = g_centers[g * 3 + 1];
    const float cz = g_centers[g * 3 + 2];

    float dd[32];
#pragma unroll
    for (int j = 0; j < 32; j++) {
        int idx = tid + j * 256;
        float dx = __fsub_rn(cx, p[idx * 3 + 0]);
        float dy = __fsub_rn(cy, p[idx * 3 + 1]);
        float dz = __fsub_rn(cz, p[idx * 3 + 2]);
        dd[j] = __fadd_rn(__fadd_rn(__fmul_rn(dx, dx), __fmul_rn(dy, dy)),
                          __fmul_rn(dz, dz));
    }
    unsigned mask = 0u;
    __shared__ float swv[8];
    __shared__ int swi[8];
    __shared__ int ssel;
    __shared__ int sel[32];

    for (int it = 0; it < 32; it++) {
        float bv = 3.0e38f;
        int bi = 0x7fffffff;
#pragma unroll
        for (int j = 0; j < 32; j++) {
            if (!((mask >> j) & 1u)) {
                float v = dd[j];
                int pi = tid + j * 256;
                if (v < bv || (v == bv && pi < bi)) { bv = v; bi = pi; }
            }
        }
#pragma unroll
        for (int off = 16; off > 0; off >>= 1) {
            float ov = __shfl_down_sync(0xffffffffu, bv, off);
            int oi = __shfl_down_sync(0xffffffffu, bi, off);
            if (ov < bv || (ov == bv && oi < bi)) { bv = ov; bi = oi; }
        }
        if ((tid & 31) == 0) { swv[tid >> 5] = bv; swi[tid >> 5] = bi; }
        __syncthreads();
        if (tid == 0) {
            float mb = swv[0]; int mi = swi[0];
            for (int w = 1; w < 8; w++) {
                if (swv[w] < mb || (swv[w] == mb && swi[w] < mi)) { mb = swv[w]; mi = swi[w]; }
            }
            ssel = mi;
            sel[it] = mi;
        }
        __syncthreads();
        int w = ssel;
        if ((w & 255) == tid) mask |= (1u << (w >> 8));
    }
    if (tid < 32) {
        int pi = sel[tid];
        g_nbhd[((size_t)g * 32 + tid) * 3 + 0] = p[pi * 3 + 0] - cx;
        g_nbhd[((size_t)g * 32 + tid) * 3 + 1] = p[pi * 3 + 1] - cy;
        g_nbhd[((size_t)g * 32 + tid) * 3 + 2] = p[pi * 3 + 2] - cz;
    }
}

// ===================== E1: f1 + f2 + group max (SIMT) =====================
__global__ void e1_kernel(const float* __restrict__ W1, const float* __restrict__ b1,
                          const float* __restrict__ g1, const float* __restrict__ be1,
                          const float* __restrict__ m1, const float* __restrict__ v1,
                          const float* __restrict__ W2, const float* __restrict__ b2) {
    const int g = blockIdx.x;
    const int tid = threadIdx.x;

    __shared__ __align__(16) float nb[96];
    __shared__ __align__(16) float f1t[128 * 36];
    __shared__ __align__(16) float W2s[16 * 256];
    __shared__ __align__(16) float fgp[4 * 256];

    if (tid < 96) nb[tid] = g_nbhd[(size_t)g * 96 + tid];
    __syncthreads();
    {
        const int c = tid;
        float w0 = W1[c], w1 = W1[128 + c], w2 = W1[256 + c];
        float bb = b1[c];
        float sc = g1[c] * rsqrtf(v1[c] + EPSF);
        float mm = m1[c], be = be1[c];
#pragma unroll 8
        for (int r = 0; r < 32; r++) {
            float pre = fmaf(nb[r * 3 + 2], w2, fmaf(nb[r * 3 + 1], w1, fmaf(nb[r * 3 + 0], w0, bb)));
            f1t[c * 36 + r] = fmaxf((pre - mm) * sc + be, 0.0f);
        }
    }
    __syncthreads();

    const int rg = tid >> 5;
    const int cg = tid & 31;
    float acc[8][8];
#pragma unroll
    for (int i = 0; i < 8; i++)
#pragma unroll
        for (int j = 0; j < 8; j++) acc[i][j] = 0.0f;

    for (int kt = 0; kt < 8; kt++) {
        for (int i = tid; i < 1024; i += 128)
            ((float4*)W2s)[i] = ((const float4*)(W2 + kt * 4096))[i];
        __syncthreads();
#pragma unroll
        for (int kk = 0; kk < 16; kk++) {
            int k = kt * 16 + kk;
            float4 fa = *(const float4*)&f1t[k * 36 + rg * 8];
            float4 fb = *(const float4*)&f1t[k * 36 + rg * 8 + 4];
            float4 wa = *(const float4*)&W2s[kk * 256 + cg * 8];
            float4 wb = *(const float4*)&W2s[kk * 256 + cg * 8 + 4];
            float fv[8] = {fa.x, fa.y, fa.z, fa.w, fb.x, fb.y, fb.z, fb.w};
            float wv[8] = {wa.x, wa.y, wa.z, wa.w, wb.x, wb.y, wb.z, wb.w};
#pragma unroll
            for (int i = 0; i < 8; i++)
#pragma unroll
                for (int j = 0; j < 8; j++) acc[i][j] = fmaf(fv[i], wv[j], acc[i][j]);
        }
        __syncthreads();
    }
    float pm[8];
#pragma unroll
    for (int j = 0; j < 8; j++) {
        float bj = b2[cg * 8 + j];
#pragma unroll
        for (int i = 0; i < 8; i++) acc[i][j] += bj;
        float m = acc[0][j];
#pragma unroll
        for (int i = 1; i < 8; i++) m = fmaxf(m, acc[i][j]);
        pm[j] = m;
    }
#pragma unroll
    for (int i = 0; i < 8; i++) {
        size_t row = (size_t)g * 32 + rg * 8 + i;
        float4 o0 = {acc[i][0], acc[i][1], acc[i][2], acc[i][3]};
        float4 o1 = {acc[i][4], acc[i][5], acc[i][6], acc[i][7]};
        *(float4*)&g_F2[row * 256 + cg * 8] = o0;
        *(float4*)&g_F2[row * 256 + cg * 8 + 4] = o1;
    }
#pragma unroll
    for (int j = 0; j < 8; j++) fgp[rg * 256 + cg * 8 + j] = pm[j];
    __syncthreads();
    for (int c = tid; c < 256; c += 128) {
        float m = fmaxf(fmaxf(fgp[c], fgp[256 + c]), fmaxf(fgp[512 + c], fgp[768 + c]));
        g_FG[(size_t)g * 256 + c] = m;
    }
}

// ===================== weight prep: transpose + tf32 round =====================
__global__ void wprep_kernel(const float* __restrict__ W3, const float* __restrict__ W4) {
    const int k = blockIdx.x;      // 0..511
    const int tid = threadIdx.x;   // 256
    for (int n = tid; n < 512; n += 256)
        g_W3T[(size_t)n * 512 + k] = tf32_rna(W3[(size_t)k * 512 + n]);
    for (int n = tid; n < 384; n += 256)
        g_W4T[(size_t)n * 512 + k] = tf32_rna(W4[(size_t)k * 384 + n]);
}

// ===================== generic tf32 mma.sync GEMM =====================
// CTA: 256 thr (8 warps, 4x2), tile M=128 x N=128, K chunk 32.
// A fp32 (hi/lo split on the fly), B pre-rounded tf32.
// MODE 0: C -> g_Htop                         (A=g_FG,  lda=256, K=256, B=W3T)
// MODE 1: C + Htop -> bn+relu -> g_F3         (A=g_F2,  lda=256, K=256, B=W3T+256)
// MODE 2: group-max(C) + b4 -> out            (A=g_F3,  lda=512, K=512, B=W4T)
#define LDP 33
#define GEMM_SMEM_BASE (3 * 128 * LDP * 4)
#define GEMM_SMEM_M1 (GEMM_SMEM_BASE + (512 + 256) * 4)

template <int KTOT, int MODE>
__global__ void __launch_bounds__(256, 2) mma_gemm(
    const float* __restrict__ p0, const float* __restrict__ p1,
    const float* __restrict__ p2, const float* __restrict__ p3,
    const float* __restrict__ p4, float* __restrict__ outp) {
    extern __shared__ __align__(16) float sm[];
    float* As_hi = sm;
    float* As_lo = sm + 128 * LDP;
    float* Bs = sm + 2 * 128 * LDP;

    const int tid = threadIdx.x;
    const int wid = tid >> 5, lane = tid & 31;
    const int gid = lane >> 2, tig = lane & 3;
    const int wm = (wid >> 1) * 32, wn = (wid & 1) * 64;
    const size_t row0 = (size_t)blockIdx.x * 128;
    const int n0 = blockIdx.y * 128;

    const float* A;
    const float* B;
    int lda;
    if (MODE == 0) { A = g_FG; lda = 256; B = g_W3T; }
    else if (MODE == 1) { A = g_F2; lda = 256; B = g_W3T + 256; }
    else { A = g_F3; lda = 512; B = g_W4T; }

    float* Hs = sm + 3 * 128 * LDP;       // MODE1: [4][128]
    float* scs = Hs + 512;
    float* bbs = scs + 128;
    if (MODE == 1) {
        for (int i = tid; i < 512; i += 256)
            Hs[i] = g_Htop[((size_t)blockIdx.x * 4 + (i >> 7)) * 512 + n0 + (i & 127)];
        for (int c = tid; c < 128; c += 256) {
            int gc = n0 + c;
            float sc = p1[gc] * rsqrtf(p4[gc] + EPSF);   // g2 * rsqrt(v2+eps)
            scs[c] = sc;
            bbs[c] = p2[gc] + (p0[gc] - p3[gc]) * sc;    // be2 + (b3-m2)*sc
        }
    }

    float acc[2][8][4];
#pragma unroll
    for (int m = 0; m < 2; m++)
#pragma unroll
        for (int n = 0; n < 8; n++)
#pragma unroll
            for (int q = 0; q < 4; q++) acc[m][n][q] = 0.0f;

    const int NKT = KTOT / 32;
    for (int kt = 0; kt < NKT; kt++) {
        const int kc0 = kt * 32;
        float4 av[4], bv[4];
#pragma unroll
        for (int it = 0; it < 4; it++) {
            int idx = tid + it * 256;
            int r = idx >> 3, q = idx & 7;
            av[it] = *(const float4*)&A[(row0 + r) * lda + kc0 + q * 4];
            bv[it] = *(const float4*)&B[(size_t)(n0 + r) * 512 + kc0 + q * 4];
        }
        __syncthreads();   // prior chunk's compute done before overwrite
#pragma unroll
        for (int it = 0; it < 4; it++) {
            int idx = tid + it * 256;
            int r = idx >> 3, q = idx & 7;
            float vv[4] = {av[it].x, av[it].y, av[it].z, av[it].w};
            float wv[4] = {bv[it].x, bv[it].y, bv[it].z, bv[it].w};
#pragma unroll
            for (int j = 0; j < 4; j++) {
                float h = tf32_rna(vv[j]);
                As_hi[r * LDP + q * 4 + j] = h;
                As_lo[r * LDP + q * 4 + j] = vv[j] - h;
                Bs[r * LDP + q * 4 + j] = wv[j];
            }
        }
        __syncthreads();

#pragma unroll
        for (int ks = 0; ks < 4; ks++) {
            const int kb = ks * 8;
            uint32_t ah[2][4], al[2][4], bf[8][2];
            const uint32_t* uh = (const uint32_t*)As_hi;
            const uint32_t* ul = (const uint32_t*)As_lo;
            const uint32_t* ub = (const uint32_t*)Bs;
#pragma unroll
            for (int m = 0; m < 2; m++) {
                int rb = (wm + m * 16 + gid) * LDP + kb + tig;
                ah[m][0] = uh[rb];            ah[m][1] = uh[rb + 8 * LDP];
                ah[m][2] = uh[rb + 4];        ah[m][3] = uh[rb + 8 * LDP + 4];
                al[m][0] = ul[rb];            al[m][1] = ul[rb + 8 * LDP];
                al[m][2] = ul[rb + 4];        al[m][3] = ul[rb + 8 * LDP + 4];
            }
#pragma unroll
            for (int n = 0; n < 8; n++) {
                int nb = (wn + n * 8 + gid) * LDP + kb + tig;
                bf[n][0] = ub[nb];
                bf[n][1] = ub[nb + 4];
            }
#pragma unroll
            for (int m = 0; m < 2; m++)
#pragma unroll
                for (int n = 0; n < 8; n++) {
                    mma16n8k8(acc[m][n], ah[m], bf[n]);
                    mma16n8k8(acc[m][n], al[m], bf[n]);
                }
        }
    }

    // ---------------- epilogues ----------------
    if (MODE == 0) {
#pragma unroll
        for (int m = 0; m < 2; m++)
#pragma unroll
            for (int n = 0; n < 8; n++) {
                size_t r = row0 + wm + m * 16 + gid;
                int c = n0 + wn + n * 8 + 2 * tig;
                float2 lo = {acc[m][n][0], acc[m][n][1]};
                float2 hi = {acc[m][n][2], acc[m][n][3]};
                *(float2*)&g_Htop[r * 512 + c] = lo;
                *(float2*)&g_Htop[(r + 8) * 512 + c] = hi;
            }
    } else if (MODE == 1) {
        const int gi = wid >> 1;
#pragma unroll
        for (int m = 0; m < 2; m++)
#pragma unroll
            for (int n = 0; n < 8; n++) {
                int cl = wn + n * 8 + 2 * tig;
                float s0 = scs[cl], s1 = scs[cl + 1];
                float bb0 = bbs[cl], bb1 = bbs[cl + 1];
                float h0 = Hs[gi * 128 + cl], h1 = Hs[gi * 128 + cl + 1];
                size_t r = row0 + wm + m * 16 + gid;
                float2 lo, hi;
                lo.x = fmaxf(fmaf(acc[m][n][0] + h0, s0, bb0), 0.0f);
                lo.y = fmaxf(fmaf(acc[m][n][1] + h1, s1, bb1), 0.0f);
                hi.x = fmaxf(fmaf(acc[m][n][2] + h0, s0, bb0), 0.0f);
                hi.y = fmaxf(fmaf(acc[m][n][3] + h1, s1, bb1), 0.0f);
                *(float2*)&g_F3[r * 512 + n0 + cl] = lo;
                *(float2*)&g_F3[(r + 8) * 512 + n0 + cl] = hi;
            }
    } else {
        const int g = blockIdx.x * 4 + (wid >> 1);
#pragma unroll
        for (int n = 0; n < 8; n++) {
            float v0 = fmaxf(fmaxf(acc[0][n][0], acc[0][n][2]),
                             fmaxf(acc[1][n][0], acc[1][n][2]));
            float v1 = fmaxf(fmaxf(acc[0][n][1], acc[0][n][3]),
                             fmaxf(acc[1][n][1], acc[1][n][3]));
#pragma unroll
            for (int off = 4; off < 32; off <<= 1) {
                v0 = fmaxf(v0, __shfl_xor_sync(0xffffffffu, v0, off));
                v1 = fmaxf(v1, __shfl_xor_sync(0xffffffffu, v1, off));
            }
            if (gid == 0) {
                int c = n0 + wn + n * 8 + 2 * tig;
                outp[(size_t)g * 384 + c] = v0 + p0[c];       // +b4
                outp[(size_t)g * 384 + c + 1] = v1 + p0[c + 1];
            }
        }
    }
}

// ===================== pos embed + cls =====================
__global__ void pos_kernel(const float* __restrict__ Wp1, const float* __restrict__ bp1,
                           const float* __restrict__ Wp2, const float* __restrict__ bp2,
                           const float* __restrict__ cls_pos, float* __restrict__ out) {
    const int row = blockIdx.x;
    const int b = blockIdx.y;
    const int tid = threadIdx.x;
    float* op = out + (size_t)NB * NG * ENC + ((size_t)b * (NG + 1) + row) * ENC;
    if (row == 0) {
        for (int c = tid; c < ENC; c += 128) op[c] = cls_pos[c];
        return;
    }
    const int g = b * NG + row - 1;
    float cx = g_centers[g * 3 + 0], cy = g_centers[g * 3 + 1], cz = g_centers[g * 3 + 2];
    __shared__ float h[128];
    {
        float pre = fmaf(cz, Wp1[256 + tid], fmaf(cy, Wp1[128 + tid], fmaf(cx, Wp1[tid], bp1[tid])));
        float x3 = pre * pre * pre;
        float inner = 0.7978845608028654f * fmaf(0.044715f, x3, pre);
        h[tid] = 0.5f * pre * (1.0f + tanhf(inner));
    }
    __syncthreads();
#pragma unroll
    for (int j = 0; j < 3; j++) {
        int c = tid + 128 * j;
        float a = bp2[c];
        for (int k = 0; k < 128; k++) a = fmaf(h[k], Wp2[k * 384 + c], a);
        op[c] = a;
    }
}

// ============================ launch ============================
extern "C" void kernel_launch(void* const* d_in, const int* in_sizes, int n_in,
                              void* d_out, int out_size) {
    const float* pts = (const float*)d_in[0];
    const float* W1 = (const float*)d_in[1];
    const float* b1 = (const float*)d_in[2];
    const float* g1 = (const float*)d_in[3];
    const float* be1 = (const float*)d_in[4];
    const float* m1 = (const float*)d_in[5];
    const float* v1 = (const float*)d_in[6];
    const float* W2 = (const float*)d_in[7];
    const float* b2 = (const float*)d_in[8];
    const float* W3 = (const float*)d_in[9];
    const float* b3 = (const float*)d_in[10];
    const float* g2 = (const float*)d_in[11];
    const float* be2 = (const float*)d_in[12];
    const float* m2 = (const float*)d_in[13];
    const float* v2 = (const float*)d_in[14];
    const float* W4 = (const float*)d_in[15];
    const float* b4 = (const float*)d_in[16];
    const float* Wp1 = (const float*)d_in[17];
    const float* bp1 = (const float*)d_in[18];
    const float* Wp2 = (const float*)d_in[19];
    const float* bp2 = (const float*)d_in[20];
    const float* cls_pos = (const float*)d_in[21];
    float* out = (float*)d_out;

    cudaFuncSetAttribute(mma_gemm<256, 0>, cudaFuncAttributeMaxDynamicSharedMemorySize, GEMM_SMEM_BASE);
    cudaFuncSetAttribute(mma_gemm<256, 1>, cudaFuncAttributeMaxDynamicSharedMemorySize, GEMM_SMEM_M1);
    cudaFuncSetAttribute(mma_gemm<512, 2>, cudaFuncAttributeMaxDynamicSharedMemorySize, GEMM_SMEM_BASE);

    fps_kernel<<<NB, 1024>>>(pts);
    knn_kernel<<<NB * NG, 256>>>(pts);
    e1_kernel<<<NB * NG, 128>>>(W1, b1, g1, be1, m1, v1, W2, b2);
    wprep_kernel<<<512, 256>>>(W3, W4);
    // Htop = FG @ W3_top
    mma_gemm<256, 0><<<dim3(64, 4), 256, GEMM_SMEM_BASE>>>(
        nullptr, nullptr, nullptr, nullptr, nullptr, nullptr);
    // F3 = relu(bn(Htop + F2 @ W3_bot + b3))
    mma_gemm<256, 1><<<dim3(2048, 4), 256, GEMM_SMEM_M1>>>(
        b3, g2, be2, m2, v2, nullptr);
    // x = max_group(F3 @ W4) + b4
    mma_gemm<512, 2><<<dim3(2048, 3), 256, GEMM_SMEM_BASE>>>(
        b4, nullptr, nullptr, nullptr, nullptr, out);
    pos_kernel<<<dim3(NG + 1, NB), 128>>>(Wp1, bp1, Wp2, bp2, cls_pos, out);
}

// round 5
// speedup vs baseline: 2.2537x; 1.7633x over previous
#include <cuda_runtime.h>
#include <math.h>
#include <stdint.h>

#define NB 16
#define NP 8192
#define NG 512
#define NM 32
#define ENC 384
#define EPSF 1e-5f

// ---------------- scratch ----------------
__device__ float g_centers[NB * NG * 3];
__device__ float g_nbhd[NB * NG * NM * 3];
__device__ float g_F2[(size_t)NB * NG * NM * 256];   // tf32-rounded
__device__ float g_FG[NB * NG * 256];                // tf32-rounded
__device__ float g_Htop[NB * NG * 512];              // fp32
__device__ float g_F3[(size_t)NB * NG * NM * 512];   // tf32-rounded
__device__ float g_W2T[256 * 128];                   // W2^T tf32
__device__ float g_W3T[512 * 512];                   // W3^T tf32
__device__ float g_W4T[384 * 512];                   // W4^T tf32

__device__ __forceinline__ float tf32_rna(float x) {
    uint32_t u;
    asm("cvt.rna.tf32.f32 %0, %1;" : "=r"(u) : "f"(x));
    return __uint_as_float(u);
}
__device__ __forceinline__ uint32_t smem_u32(const void* p) {
    uint32_t a;
    asm("{ .reg .u64 t; cvta.to.shared.u64 t, %1; cvt.u32.u64 %0, t; }" : "=r"(a) : "l"(p));
    return a;
}
__device__ __forceinline__ void mma16n8k8(float* c, const uint32_t* a, const uint32_t* b) {
    asm volatile(
        "mma.sync.aligned.m16n8k8.row.col.f32.tf32.tf32.f32 "
        "{%0,%1,%2,%3}, {%4,%5,%6,%7}, {%8,%9}, {%0,%1,%2,%3};"
        : "+f"(c[0]), "+f"(c[1]), "+f"(c[2]), "+f"(c[3])
        : "r"(a[0]), "r"(a[1]), "r"(a[2]), "r"(a[3]), "r"(b[0]), "r"(b[1]));
}
#define CP_ASYNC16(dst_u32, src) \
    asm volatile("cp.async.cg.shared.global [%0], [%1], 16;" :: "r"(dst_u32), "l"(src))
#define CP_COMMIT() asm volatile("cp.async.commit_group;" ::: "memory")
#define CP_WAIT(n) asm volatile("cp.async.wait_group %0;" :: "n"(n) : "memory")

#define LDP 36
#define TILE (128 * LDP)

// ============================ FPS =============================
// one block per batch, 512 threads, 16 pts/thread in regs, points mirrored in smem
#define FPS_SMEM (3 * NP * 4)
__global__ void __launch_bounds__(512, 1) fps_kernel(const float* __restrict__ pts) {
    extern __shared__ float fsm[];
    float* spx = fsm;
    float* spy = fsm + NP;
    float* spz = fsm + 2 * NP;

    const int b = blockIdx.x;
    const float* p = pts + (size_t)b * NP * 3;
    const int tid = threadIdx.x;
    const int lane = tid & 31, wid = tid >> 5;

    float px[16], py[16], pz[16], dd[16];
#pragma unroll
    for (int i = 0; i < 16; i++) {
        int idx = tid + i * 512;
        float x = p[idx * 3 + 0], y = p[idx * 3 + 1], z = p[idx * 3 + 2];
        px[i] = x; py[i] = y; pz[i] = z; dd[i] = 1e10f;
        spx[idx] = x; spy[idx] = y; spz[idx] = z;
    }
    __shared__ int sFar;
    __shared__ float swv[16];
    __shared__ int swi[16];
    if (tid == 0) sFar = 0;
    __syncthreads();

    for (int s = 0; s < NG; s++) {
        const int far = sFar;
        const float cx = spx[far], cy = spy[far], cz = spz[far];
        if (tid == 0) {
            g_centers[(b * NG + s) * 3 + 0] = cx;
            g_centers[(b * NG + s) * 3 + 1] = cy;
            g_centers[(b * NG + s) * 3 + 2] = cz;
        }
        float bv = -1.0f;
        int bi = 0;
#pragma unroll
        for (int i = 0; i < 16; i++) {
            float dx = __fsub_rn(px[i], cx);
            float dy = __fsub_rn(py[i], cy);
            float dz = __fsub_rn(pz[i], cz);
            float d = __fadd_rn(__fadd_rn(__fmul_rn(dx, dx), __fmul_rn(dy, dy)),
                                __fmul_rn(dz, dz));
            dd[i] = fminf(dd[i], d);
            if (dd[i] > bv) { bv = dd[i]; bi = tid + i * 512; }
        }
#pragma unroll
        for (int off = 16; off > 0; off >>= 1) {
            float ov = __shfl_xor_sync(0xffffffffu, bv, off);
            int oi = __shfl_xor_sync(0xffffffffu, bi, off);
            if (ov > bv || (ov == bv && oi < bi)) { bv = ov; bi = oi; }
        }
        if (lane == 0) { swv[wid] = bv; swi[wid] = bi; }
        __syncthreads();
        if (wid == 0) {
            float v = (lane < 16) ? swv[lane] : -2.0f;
            int ii = (lane < 16) ? swi[lane] : 0x7fffffff;
#pragma unroll
            for (int off = 8; off > 0; off >>= 1) {
                float ov = __shfl_xor_sync(0xffffffffu, v, off);
                int oi = __shfl_xor_sync(0xffffffffu, ii, off);
                if (ov > v || (ov == v && oi < ii)) { v = ov; ii = oi; }
            }
            if (lane == 0) sFar = ii;
        }
        __syncthreads();
    }
}

// ============================ kNN =============================
__global__ void knn_kernel(const float* __restrict__ pts) {
    const int g = blockIdx.x;
    const int b = g >> 9;
    const float* p = pts + (size_t)b * NP * 3;
    const int tid = threadIdx.x;

    const float cx = g_centers[g * 3 + 0];
    const float cy = g_centers[g * 3 + 1];
    const float cz = g_centers[g * 3 + 2];

    float dd[32];
#pragma unroll
    for (int j = 0; j < 32; j++) {
        int idx = tid + j * 256;
        float dx = __fsub_rn(cx, p[idx * 3 + 0]);
        float dy = __fsub_rn(cy, p[idx * 3 + 1]);
        float dz = __fsub_rn(cz, p[idx * 3 + 2]);
        dd[j] = __fadd_rn(__fadd_rn(__fmul_rn(dx, dx), __fmul_rn(dy, dy)),
                          __fmul_rn(dz, dz));
    }
    unsigned mask = 0u;
    __shared__ float swv[8];
    __shared__ int swi[8];
    __shared__ int ssel;
    __shared__ int sel[32];

    for (int it = 0; it < 32; it++) {
        float bv = 3.0e38f;
        int bi = 0x7fffffff;
#pragma unroll
        for (int j = 0; j < 32; j++) {
            if (!((mask >> j) & 1u)) {
                float v = dd[j];
                int pi = tid + j * 256;
                if (v < bv || (v == bv && pi < bi)) { bv = v; bi = pi; }
            }
        }
#pragma unroll
        for (int off = 16; off > 0; off >>= 1) {
            float ov = __shfl_down_sync(0xffffffffu, bv, off);
            int oi = __shfl_down_sync(0xffffffffu, bi, off);
            if (ov < bv || (ov == bv && oi < bi)) { bv = ov; bi = oi; }
        }
        if ((tid & 31) == 0) { swv[tid >> 5] = bv; swi[tid >> 5] = bi; }
        __syncthreads();
        if (tid == 0) {
            float mb = swv[0]; int mi = swi[0];
            for (int w = 1; w < 8; w++) {
                if (swv[w] < mb || (swv[w] == mb && swi[w] < mi)) { mb = swv[w]; mi = swi[w]; }
            }
            ssel = mi;
            sel[it] = mi;
        }
        __syncthreads();
        int w = ssel;
        if ((w & 255) == tid) mask |= (1u << (w >> 8));
    }
    if (tid < 32) {
        int pi = sel[tid];
        g_nbhd[((size_t)g * 32 + tid) * 3 + 0] = p[pi * 3 + 0] - cx;
        g_nbhd[((size_t)g * 32 + tid) * 3 + 1] = p[pi * 3 + 1] - cy;
        g_nbhd[((size_t)g * 32 + tid) * 3 + 2] = p[pi * 3 + 2] - cz;
    }
}

// ===================== weight prep: transpose + tf32 round =====================
__global__ void wprep_kernel(const float* __restrict__ W2, const float* __restrict__ W3,
                             const float* __restrict__ W4) {
    const int k = blockIdx.x;      // 0..511
    const int tid = threadIdx.x;   // 256
    for (int n = tid; n < 512; n += 256)
        g_W3T[(size_t)n * 512 + k] = tf32_rna(W3[(size_t)k * 512 + n]);
    for (int n = tid; n < 384; n += 256)
        g_W4T[(size_t)n * 512 + k] = tf32_rna(W4[(size_t)k * 384 + n]);
    if (k < 128) {
        for (int n = tid; n < 256; n += 256)
            g_W2T[(size_t)n * 128 + k] = tf32_rna(W2[(size_t)k * 256 + n]);
    }
}

// ===================== E1 via tensor cores =====================
// CTA: 128 rows (4 groups) x 128 cols of f2 = f1(in-smem) @ W2T, K=128
#define LDPA 132
#define E1_SMEM ((128 * LDPA + 2 * TILE + 384 + 5 * 128) * 4)
__global__ void __launch_bounds__(256, 2) e1_tc(
    const float* __restrict__ W1, const float* __restrict__ b1,
    const float* __restrict__ g1, const float* __restrict__ be1,
    const float* __restrict__ m1, const float* __restrict__ v1,
    const float* __restrict__ b2) {
    extern __shared__ __align__(16) float sm[];
    float* As = sm;                       // [128][LDPA] f1 tf32
    float* Bs = sm + 128 * LDPA;          // [2][TILE]
    float* nbs = Bs + 2 * TILE;           // 384
    float* wxs = nbs + 384;               // 128
    float* wys = wxs + 128;
    float* wzs = wys + 128;
    float* scs = wzs + 128;
    float* bbs = scs + 128;
    const uint32_t BsU = smem_u32(Bs);

    const int tid = threadIdx.x;
    const int wid = tid >> 5, lane = tid & 31;
    const int gid = lane >> 2, tig = lane & 3;
    const int wm = (wid >> 1) * 32, wn = (wid & 1) * 64;
    const size_t row0 = (size_t)blockIdx.x * 128;
    const int n0 = blockIdx.y * 128;

    // prefetch B chunks 0,1
#pragma unroll
    for (int s = 0; s < 2; s++) {
#pragma unroll
        for (int it = 0; it < 4; it++) {
            int idx = tid + it * 256;
            int r = idx >> 3, q = idx & 7;
            CP_ASYNC16(BsU + (uint32_t)(s * TILE + r * LDP + q * 4) * 4,
                       &g_W2T[(size_t)(n0 + r) * 128 + s * 32 + q * 4]);
        }
        CP_COMMIT();
    }

    if (tid < 128) {
        int c = tid;
        wxs[c] = W1[c]; wys[c] = W1[128 + c]; wzs[c] = W1[256 + c];
        float sc = g1[c] * rsqrtf(v1[c] + EPSF);
        scs[c] = sc;
        bbs[c] = (b1[c] - m1[c]) * sc + be1[c];
    }
    for (int i = tid; i < 384; i += 256) nbs[i] = g_nbhd[row0 * 3 + i];
    __syncthreads();

    // f1 -> As (tf32)
    for (int idx = tid; idx < 16384; idx += 256) {
        int c = idx & 127, r = idx >> 7;
        float dot = fmaf(nbs[r * 3 + 2], wzs[c],
                    fmaf(nbs[r * 3 + 1], wys[c],
                         nbs[r * 3 + 0] * wxs[c]));
        float val = fmaf(dot, scs[c], bbs[c]);
        As[r * LDPA + c] = tf32_rna(fmaxf(val, 0.0f));
    }

    float acc[2][8][4];
#pragma unroll
    for (int m = 0; m < 2; m++)
#pragma unroll
        for (int n = 0; n < 8; n++)
#pragma unroll
            for (int q = 0; q < 4; q++) acc[m][n][q] = 0.0f;

    const uint32_t* uh = (const uint32_t*)As;
    for (int kt = 0; kt < 4; kt++) {
        if (kt < 3) { CP_WAIT(1); } else { CP_WAIT(0); }
        __syncthreads();
        const uint32_t* ub = (const uint32_t*)(Bs + (kt & 1) * TILE);
#pragma unroll
        for (int ks = 0; ks < 4; ks++) {
            const int kbA = kt * 32 + ks * 8;
            const int kbB = ks * 8;
            uint32_t ah[2][4], bf[8][2];
#pragma unroll
            for (int m = 0; m < 2; m++) {
                int rb = (wm + m * 16 + gid) * LDPA + kbA + tig;
                ah[m][0] = uh[rb];       ah[m][1] = uh[rb + 8 * LDPA];
                ah[m][2] = uh[rb + 4];   ah[m][3] = uh[rb + 8 * LDPA + 4];
            }
#pragma unroll
            for (int n = 0; n < 8; n++) {
                int nb = (wn + n * 8 + gid) * LDP + kbB + tig;
                bf[n][0] = ub[nb];
                bf[n][1] = ub[nb + 4];
            }
#pragma unroll
            for (int m = 0; m < 2; m++)
#pragma unroll
                for (int n = 0; n < 8; n++) mma16n8k8(acc[m][n], ah[m], bf[n]);
        }
        __syncthreads();
        if (kt + 2 < 4) {
            int s = kt & 1;
#pragma unroll
            for (int it = 0; it < 4; it++) {
                int idx = tid + it * 256;
                int r = idx >> 3, q = idx & 7;
                CP_ASYNC16(BsU + (uint32_t)(s * TILE + r * LDP + q * 4) * 4,
                           &g_W2T[(size_t)(n0 + r) * 128 + (kt + 2) * 32 + q * 4]);
            }
            CP_COMMIT();
        }
    }

    // epilogue: write F2 (rounded, +b2), group-max -> FG (rounded)
    const int g = blockIdx.x * 4 + (wid >> 1);
#pragma unroll
    for (int n = 0; n < 8; n++) {
        int c0 = wn + n * 8 + 2 * tig;
        float bb0 = b2[n0 + c0], bb1 = b2[n0 + c0 + 1];
#pragma unroll
        for (int m = 0; m < 2; m++) {
            size_t r = row0 + wm + m * 16 + gid;
            g_F2[r * 256 + n0 + c0] = tf32_rna(acc[m][n][0] + bb0);
            g_F2[r * 256 + n0 + c0 + 1] = tf32_rna(acc[m][n][1] + bb1);
            g_F2[(r + 8) * 256 + n0 + c0] = tf32_rna(acc[m][n][2] + bb0);
            g_F2[(r + 8) * 256 + n0 + c0 + 1] = tf32_rna(acc[m][n][3] + bb1);
        }
        float v0 = fmaxf(fmaxf(acc[0][n][0], acc[0][n][2]),
                         fmaxf(acc[1][n][0], acc[1][n][2]));
        float v1 = fmaxf(fmaxf(acc[0][n][1], acc[0][n][3]),
                         fmaxf(acc[1][n][1], acc[1][n][3]));
#pragma unroll
        for (int off = 4; off < 32; off <<= 1) {
            v0 = fmaxf(v0, __shfl_xor_sync(0xffffffffu, v0, off));
            v1 = fmaxf(v1, __shfl_xor_sync(0xffffffffu, v1, off));
        }
        if (gid == 0) {
            g_FG[(size_t)g * 256 + n0 + c0] = tf32_rna(v0 + bb0);
            g_FG[(size_t)g * 256 + n0 + c0 + 1] = tf32_rna(v1 + bb1);
        }
    }
}

// ===================== generic single-pass tf32 GEMM (cp.async dbl-buffered) =====================
// MODE 0: Htop = FG @ W3T[:, :256]            (fp32 out)
// MODE 1: F3 = rna(relu(bn(Htop + F2 @ W3T[:, 256:])))
// MODE 2: out = group-max(F3 @ W4T) + b4
#define GEMM_SMEM_BASE (4 * TILE * 4)
#define GEMM_SMEM_M1 (GEMM_SMEM_BASE + (512 + 256) * 4)

template <int KTOT, int MODE>
__global__ void __launch_bounds__(256, 2) mma_gemm(
    const float* __restrict__ p0, const float* __restrict__ p1,
    const float* __restrict__ p2, const float* __restrict__ p3,
    const float* __restrict__ p4, float* __restrict__ outp) {
    extern __shared__ __align__(16) float sm[];
    float* As = sm;                 // [2][TILE]
    float* Bs = sm + 2 * TILE;      // [2][TILE]
    const uint32_t AsU = smem_u32(As);
    const uint32_t BsU = smem_u32(Bs);

    const int tid = threadIdx.x;
    const int wid = tid >> 5, lane = tid & 31;
    const int gid = lane >> 2, tig = lane & 3;
    const int wm = (wid >> 1) * 32, wn = (wid & 1) * 64;
    const size_t row0 = (size_t)blockIdx.x * 128;
    const int n0 = blockIdx.y * 128;

    const float* A;
    const float* B;
    int lda;
    if (MODE == 0) { A = g_FG; lda = 256; B = g_W3T; }
    else if (MODE == 1) { A = g_F2; lda = 256; B = g_W3T + 256; }
    else { A = g_F3; lda = 512; B = g_W4T; }

    float* Hs = sm + 4 * TILE;      // MODE1: [4][128]
    float* scs = Hs + 512;
    float* bbs = scs + 128;
    if (MODE == 1) {
        for (int i = tid; i < 512; i += 256)
            Hs[i] = g_Htop[((size_t)blockIdx.x * 4 + (i >> 7)) * 512 + n0 + (i & 127)];
        for (int c = tid; c < 128; c += 256) {
            int gc = n0 + c;
            float sc = p1[gc] * rsqrtf(p4[gc] + EPSF);
            scs[c] = sc;
            bbs[c] = p2[gc] + (p0[gc] - p3[gc]) * sc;
        }
    }

    const int NKT = KTOT / 32;
    // prologue: stage chunks 0, 1
#pragma unroll
    for (int s = 0; s < 2; s++) {
#pragma unroll
        for (int it = 0; it < 4; it++) {
            int idx = tid + it * 256;
            int r = idx >> 3, q = idx & 7;
            CP_ASYNC16(AsU + (uint32_t)(s * TILE + r * LDP + q * 4) * 4,
                       &A[(row0 + r) * lda + s * 32 + q * 4]);
            CP_ASYNC16(BsU + (uint32_t)(s * TILE + r * LDP + q * 4) * 4,
                       &B[(size_t)(n0 + r) * 512 + s * 32 + q * 4]);
        }
        CP_COMMIT();
    }

    float acc[2][8][4];
#pragma unroll
    for (int m = 0; m < 2; m++)
#pragma unroll
        for (int n = 0; n < 8; n++)
#pragma unroll
            for (int q = 0; q < 4; q++) acc[m][n][q] = 0.0f;

    for (int kt = 0; kt < NKT; kt++) {
        if (kt < NKT - 1) { CP_WAIT(1); } else { CP_WAIT(0); }
        __syncthreads();
        const uint32_t* uh = (const uint32_t*)(As + (kt & 1) * TILE);
        const uint32_t* ub = (const uint32_t*)(Bs + (kt & 1) * TILE);
#pragma unroll
        for (int ks = 0; ks < 4; ks++) {
            const int kb = ks * 8;
            uint32_t ah[2][4], bf[8][2];
#pragma unroll
            for (int m = 0; m < 2; m++) {
                int rb = (wm + m * 16 + gid) * LDP + kb + tig;
                ah[m][0] = uh[rb];       ah[m][1] = uh[rb + 8 * LDP];
                ah[m][2] = uh[rb + 4];   ah[m][3] = uh[rb + 8 * LDP + 4];
            }
#pragma unroll
            for (int n = 0; n < 8; n++) {
                int nb = (wn + n * 8 + gid) * LDP + kb + tig;
                bf[n][0] = ub[nb];
                bf[n][1] = ub[nb + 4];
            }
#pragma unroll
            for (int m = 0; m < 2; m++)
#pragma unroll
                for (int n = 0; n < 8; n++) mma16n8k8(acc[m][n], ah[m], bf[n]);
        }
        __syncthreads();
        if (kt + 2 < NKT) {
            int s = kt & 1;
            int kc0 = (kt + 2) * 32;
#pragma unroll
            for (int it = 0; it < 4; it++) {
                int idx = tid + it * 256;
                int r = idx >> 3, q = idx & 7;
                CP_ASYNC16(AsU + (uint32_t)(s * TILE + r * LDP + q * 4) * 4,
                           &A[(row0 + r) * lda + kc0 + q * 4]);
                CP_ASYNC16(BsU + (uint32_t)(s * TILE + r * LDP + q * 4) * 4,
                           &B[(size_t)(n0 + r) * 512 + kc0 + q * 4]);
            }
            CP_COMMIT();
        }
    }

    // ---------------- epilogues ----------------
    if (MODE == 0) {
#pragma unroll
        for (int m = 0; m < 2; m++)
#pragma unroll
            for (int n = 0; n < 8; n++) {
                size_t r = row0 + wm + m * 16 + gid;
                int c = n0 + wn + n * 8 + 2 * tig;
                float2 lo = {acc[m][n][0], acc[m][n][1]};
                float2 hi = {acc[m][n][2], acc[m][n][3]};
                *(float2*)&g_Htop[r * 512 + c] = lo;
                *(float2*)&g_Htop[(r + 8) * 512 + c] = hi;
            }
    } else if (MODE == 1) {
        const int gi = wid >> 1;
#pragma unroll
        for (int m = 0; m < 2; m++)
#pragma unroll
            for (int n = 0; n < 8; n++) {
                int cl = wn + n * 8 + 2 * tig;
                float s0 = scs[cl], s1 = scs[cl + 1];
                float bb0 = bbs[cl], bb1 = bbs[cl + 1];
                float h0 = Hs[gi * 128 + cl], h1 = Hs[gi * 128 + cl + 1];
                size_t r = row0 + wm + m * 16 + gid;
                float2 lo, hi;
                lo.x = tf32_rna(fmaxf(fmaf(acc[m][n][0] + h0, s0, bb0), 0.0f));
                lo.y = tf32_rna(fmaxf(fmaf(acc[m][n][1] + h1, s1, bb1), 0.0f));
                hi.x = tf32_rna(fmaxf(fmaf(acc[m][n][2] + h0, s0, bb0), 0.0f));
                hi.y = tf32_rna(fmaxf(fmaf(acc[m][n][3] + h1, s1, bb1), 0.0f));
                *(float2*)&g_F3[r * 512 + n0 + cl] = lo;
                *(float2*)&g_F3[(r + 8) * 512 + n0 + cl] = hi;
            }
    } else {
        const int g = blockIdx.x * 4 + (wid >> 1);
#pragma unroll
        for (int n = 0; n < 8; n++) {
            float v0 = fmaxf(fmaxf(acc[0][n][0], acc[0][n][2]),
                             fmaxf(acc[1][n][0], acc[1][n][2]));
            float v1 = fmaxf(fmaxf(acc[0][n][1], acc[0][n][3]),
                             fmaxf(acc[1][n][1], acc[1][n][3]));
#pragma unroll
            for (int off = 4; off < 32; off <<= 1) {
                v0 = fmaxf(v0, __shfl_xor_sync(0xffffffffu, v0, off));
                v1 = fmaxf(v1, __shfl_xor_sync(0xffffffffu, v1, off));
            }
            if (gid == 0) {
                int c = n0 + wn + n * 8 + 2 * tig;
                outp[(size_t)g * 384 + c] = v0 + p0[c];
                outp[(size_t)g * 384 + c + 1] = v1 + p0[c + 1];
            }
        }
    }
}

// ===================== pos embed + cls =====================
__global__ void pos_kernel(const float* __restrict__ Wp1, const float* __restrict__ bp1,
                           const float* __restrict__ Wp2, const float* __restrict__ bp2,
                           const float* __restrict__ cls_pos, float* __restrict__ out) {
    const int row = blockIdx.x;
    const int b = blockIdx.y;
    const int tid = threadIdx.x;
    float* op = out + (size_t)NB * NG * ENC + ((size_t)b * (NG + 1) + row) * ENC;
    if (row == 0) {
        for (int c = tid; c < ENC; c += 128) op[c] = cls_pos[c];
        return;
    }
    const int g = b * NG + row - 1;
    float cx = g_centers[g * 3 + 0], cy = g_centers[g * 3 + 1], cz = g_centers[g * 3 + 2];
    __shared__ float h[128];
    {
        float pre = fmaf(cz, Wp1[256 + tid], fmaf(cy, Wp1[128 + tid], fmaf(cx, Wp1[tid], bp1[tid])));
        float x3 = pre * pre * pre;
        float inner = 0.7978845608028654f * fmaf(0.044715f, x3, pre);
        h[tid] = 0.5f * pre * (1.0f + tanhf(inner));
    }
    __syncthreads();
#pragma unroll
    for (int j = 0; j < 3; j++) {
        int c = tid + 128 * j;
        float a = bp2[c];
        for (int k = 0; k < 128; k++) a = fmaf(h[k], Wp2[k * 384 + c], a);
        op[c] = a;
    }
}

// ============================ launch ============================
extern "C" void kernel_launch(void* const* d_in, const int* in_sizes, int n_in,
                              void* d_out, int out_size) {
    const float* pts = (const float*)d_in[0];
    const float* W1 = (const float*)d_in[1];
    const float* b1 = (const float*)d_in[2];
    const float* g1 = (const float*)d_in[3];
    const float* be1 = (const float*)d_in[4];
    const float* m1 = (const float*)d_in[5];
    const float* v1 = (const float*)d_in[6];
    const float* W2 = (const float*)d_in[7];
    const float* b2 = (const float*)d_in[8];
    const float* W3 = (const float*)d_in[9];
    const float* b3 = (const float*)d_in[10];
    const float* g2 = (const float*)d_in[11];
    const float* be2 = (const float*)d_in[12];
    const float* m2 = (const float*)d_in[13];
    const float* v2 = (const float*)d_in[14];
    const float* W4 = (const float*)d_in[15];
    const float* b4 = (const float*)d_in[16];
    const float* Wp1 = (const float*)d_in[17];
    const float* bp1 = (const float*)d_in[18];
    const float* Wp2 = (const float*)d_in[19];
    const float* bp2 = (const float*)d_in[20];
    const float* cls_pos = (const float*)d_in[21];
    float* out = (float*)d_out;

    cudaFuncSetAttribute(fps_kernel, cudaFuncAttributeMaxDynamicSharedMemorySize, FPS_SMEM);
    cudaFuncSetAttribute(e1_tc, cudaFuncAttributeMaxDynamicSharedMemorySize, E1_SMEM);
    cudaFuncSetAttribute(mma_gemm<256, 0>, cudaFuncAttributeMaxDynamicSharedMemorySize, GEMM_SMEM_BASE);
    cudaFuncSetAttribute(mma_gemm<256, 1>, cudaFuncAttributeMaxDynamicSharedMemorySize, GEMM_SMEM_M1);
    cudaFuncSetAttribute(mma_gemm<512, 2>, cudaFuncAttributeMaxDynamicSharedMemorySize, GEMM_SMEM_BASE);

    fps_kernel<<<NB, 512, FPS_SMEM>>>(pts);
    knn_kernel<<<NB * NG, 256>>>(pts);
    wprep_kernel<<<512, 256>>>(W2, W3, W4);
    e1_tc<<<dim3(2048, 2), 256, E1_SMEM>>>(W1, b1, g1, be1, m1, v1, b2);
    mma_gemm<256, 0><<<dim3(64, 4), 256, GEMM_SMEM_BASE>>>(
        nullptr, nullptr, nullptr, nullptr, nullptr, nullptr);
    mma_gemm<256, 1><<<dim3(2048, 4), 256, GEMM_SMEM_M1>>>(
        b3, g2, be2, m2, v2, nullptr);
    mma_gemm<512, 2><<<dim3(2048, 3), 256, GEMM_SMEM_BASE>>>(
        b4, nullptr, nullptr, nullptr, nullptr, out);
    pos_kernel<<<dim3(NG + 1, NB), 128>>>(Wp1, bp1, Wp2, bp2, cls_pos, out);
}

// round 8
// speedup vs baseline: 3.5653x; 1.5820x over previous
#include <cuda_runtime.h>
#include <math.h>
#include <stdint.h>

#define NB 16
#define NP 8192
#define NG 512
#define NM 32
#define ENC 384
#define EPSF 1e-5f

// ---------------- scratch ----------------
__device__ float g_centers[NB * NG * 3];
__device__ float g_nbhd[NB * NG * NM * 3];
__device__ float g_F2[(size_t)NB * NG * NM * 256];   // tf32-rounded
__device__ float g_FG[NB * NG * 256];                // tf32-rounded
__device__ float g_Htop[NB * NG * 512];              // fp32
__device__ float g_F3[(size_t)NB * NG * NM * 512];   // tf32-rounded
__device__ float g_W2T[256 * 128];                   // W2^T tf32
__device__ float g_W3T[512 * 512];                   // W3^T tf32
__device__ float g_W4T[384 * 512];                   // W4^T tf32

__device__ __forceinline__ float tf32_rna(float x) {
    uint32_t u;
    asm("cvt.rna.tf32.f32 %0, %1;" : "=r"(u) : "f"(x));
    return __uint_as_float(u);
}
__device__ __forceinline__ uint32_t smem_u32(const void* p) {
    uint32_t a;
    asm("{ .reg .u64 t; cvta.to.shared.u64 t, %1; cvt.u32.u64 %0, t; }" : "=r"(a) : "l"(p));
    return a;
}
__device__ __forceinline__ void mma16n8k8(float* c, const uint32_t* a, const uint32_t* b) {
    asm volatile(
        "mma.sync.aligned.m16n8k8.row.col.f32.tf32.tf32.f32 "
        "{%0,%1,%2,%3}, {%4,%5,%6,%7}, {%8,%9}, {%0,%1,%2,%3};"
        : "+f"(c[0]), "+f"(c[1]), "+f"(c[2]), "+f"(c[3])
        : "r"(a[0]), "r"(a[1]), "r"(a[2]), "r"(a[3]), "r"(b[0]), "r"(b[1]));
}
#define CP_ASYNC16(dst_u32, src) \
    asm volatile("cp.async.cg.shared.global [%0], [%1], 16;" :: "r"(dst_u32), "l"(src))
#define CP_COMMIT() asm volatile("cp.async.commit_group;" ::: "memory")
#define CP_WAIT(n) asm volatile("cp.async.wait_group %0;" :: "n"(n) : "memory")

#define LDP 36
#define TILE (128 * LDP)

// ============================ FPS =============================
#define FPS_SMEM (3 * NP * 4)
__global__ void __launch_bounds__(512, 1) fps_kernel(const float* __restrict__ pts) {
    extern __shared__ float fsm[];
    float* spx = fsm;
    float* spy = fsm + NP;
    float* spz = fsm + 2 * NP;

    const int b = blockIdx.x;
    const float* p = pts + (size_t)b * NP * 3;
    const int tid = threadIdx.x;
    const int lane = tid & 31, wid = tid >> 5;

    float px[16], py[16], pz[16], dd[16];
#pragma unroll
    for (int i = 0; i < 16; i++) {
        int idx = tid + i * 512;
        float x = p[idx * 3 + 0], y = p[idx * 3 + 1], z = p[idx * 3 + 2];
        px[i] = x; py[i] = y; pz[i] = z; dd[i] = 1e10f;
        spx[idx] = x; spy[idx] = y; spz[idx] = z;
    }
    __shared__ int sFar;
    __shared__ float swv[16];
    __shared__ int swi[16];
    if (tid == 0) sFar = 0;
    __syncthreads();

    for (int s = 0; s < NG; s++) {
        const int far = sFar;
        const float cx = spx[far], cy = spy[far], cz = spz[far];
        if (tid == 0) {
            g_centers[(b * NG + s) * 3 + 0] = cx;
            g_centers[(b * NG + s) * 3 + 1] = cy;
            g_centers[(b * NG + s) * 3 + 2] = cz;
        }
        float bv = -1.0f;
        int bi = 0;
#pragma unroll
        for (int i = 0; i < 16; i++) {
            float dx = __fsub_rn(px[i], cx);
            float dy = __fsub_rn(py[i], cy);
            float dz = __fsub_rn(pz[i], cz);
            float d = __fadd_rn(__fadd_rn(__fmul_rn(dx, dx), __fmul_rn(dy, dy)),
                                __fmul_rn(dz, dz));
            dd[i] = fminf(dd[i], d);
            if (dd[i] > bv) { bv = dd[i]; bi = tid + i * 512; }
        }
#pragma unroll
        for (int off = 16; off > 0; off >>= 1) {
            float ov = __shfl_xor_sync(0xffffffffu, bv, off);
            int oi = __shfl_xor_sync(0xffffffffu, bi, off);
            if (ov > bv || (ov == bv && oi < bi)) { bv = ov; bi = oi; }
        }
        if (lane == 0) { swv[wid] = bv; swi[wid] = bi; }
        __syncthreads();
        if (wid == 0) {
            float v = (lane < 16) ? swv[lane] : -2.0f;
            int ii = (lane < 16) ? swi[lane] : 0x7fffffff;
#pragma unroll
            for (int off = 8; off > 0; off >>= 1) {
                float ov = __shfl_xor_sync(0xffffffffu, v, off);
                int oi = __shfl_xor_sync(0xffffffffu, ii, off);
                if (ov > v || (ov == v && oi < ii)) { v = ov; ii = oi; }
            }
            if (lane == 0) sFar = ii;
        }
        __syncthreads();
    }
}

// ============================ kNN (exact radix-select) =============================
// Set semantics: downstream consumers only max-pool over the neighborhood, so
// output order is irrelevant. Selection set matches top_k exactly:
// all d < T plus smallest-index ties d == T, T = exact 32nd-smallest distance.
__global__ void __launch_bounds__(256, 4) knn_kernel(const float* __restrict__ pts) {
    const int g = blockIdx.x;
    const int b = g >> 9;
    const float* p = pts + (size_t)b * NP * 3;
    const int tid = threadIdx.x;
    const int wid = tid >> 5;

    const float cx = g_centers[g * 3 + 0];
    const float cy = g_centers[g * 3 + 1];
    const float cz = g_centers[g * 3 + 2];

    uint32_t key[32];
#pragma unroll
    for (int j = 0; j < 32; j++) {
        int idx = tid + j * 256;
        float dx = __fsub_rn(cx, p[idx * 3 + 0]);
        float dy = __fsub_rn(cy, p[idx * 3 + 1]);
        float dz = __fsub_rn(cz, p[idx * 3 + 2]);
        float d = __fadd_rn(__fadd_rn(__fmul_rn(dx, dx), __fmul_rn(dy, dy)),
                            __fmul_rn(dz, dz));
        key[j] = __float_as_uint(d);   // d >= 0: uint order == float order
    }

    __shared__ uint32_t hist[8][256];
    __shared__ uint32_t cum_bin, cum_r;
    __shared__ int c_less, c_tie;
    __shared__ int sel[32];
    __shared__ int ties[128];

    uint32_t prefix = 0;
    uint32_t r = 32;    // 1-based rank of target (32nd smallest)

#pragma unroll 1
    for (int pass = 0; pass < 4; pass++) {
        const int shift = 24 - pass * 8;
        for (int i = tid; i < 8 * 256; i += 256) (&hist[0][0])[i] = 0;
        __syncthreads();
        const uint32_t pmask = (pass == 0) ? 0u : (0xFFFFFFFFu << (shift + 8));
#pragma unroll
        for (int j = 0; j < 32; j++) {
            if ((key[j] & pmask) == prefix)
                atomicAdd(&hist[wid][(key[j] >> shift) & 255u], 1u);
        }
        __syncthreads();
        if (wid == 0) {
            const int lane = tid & 31;
            uint32_t binc[8];
            uint32_t lsum = 0;
#pragma unroll
            for (int q = 0; q < 8; q++) {
                uint32_t s = 0;
#pragma unroll
                for (int w = 0; w < 8; w++) s += hist[w][lane * 8 + q];
                binc[q] = s;
                lsum += s;
            }
            uint32_t inc = lsum;
#pragma unroll
            for (int off = 1; off < 32; off <<= 1) {
                uint32_t v = __shfl_up_sync(0xffffffffu, inc, off);
                if (lane >= off) inc += v;
            }
            uint32_t excl = inc - lsum;
            uint32_t vote = __ballot_sync(0xffffffffu, inc >= r);
            int selLane = __ffs(vote) - 1;
            if (lane == selLane) {
                uint32_t rr = r - excl;   // 1-based within this lane's 8 bins
                uint32_t c = 0;
                int bq = 0;
#pragma unroll
                for (int q = 0; q < 8; q++) {
                    if (c + binc[q] >= rr) { bq = q; break; }
                    c += binc[q];
                }
                cum_bin = (uint32_t)(lane * 8 + bq);
                cum_r = rr - c;
            }
        }
        __syncthreads();
        prefix |= (cum_bin << shift);
        r = cum_r;
        __syncthreads();
    }
    const uint32_t T = prefix;

    if (tid == 0) { c_less = 0; c_tie = 0; }
    __syncthreads();
#pragma unroll
    for (int j = 0; j < 32; j++) {
        int pidx = tid + j * 256;
        if (key[j] < T) {
            int pos = atomicAdd(&c_less, 1);
            sel[pos] = pidx;                      // < 32 guaranteed
        } else if (key[j] == T) {
            int pos = atomicAdd(&c_tie, 1);
            if (pos < 128) ties[pos] = pidx;
        }
    }
    __syncthreads();
    if (tid == 0) {
        int need = 32 - c_less;
        int m = c_tie < 128 ? c_tie : 128;
        for (int t = 0; t < need; t++) {
            int best = 0x7fffffff, bj = 0;
            for (int j2 = 0; j2 < m; j2++)
                if (ties[j2] < best) { best = ties[j2]; bj = j2; }
            sel[c_less + t] = best;
            ties[bj] = 0x7fffffff;
        }
    }
    __syncthreads();
    if (tid < 32) {
        int pi = sel[tid];
        g_nbhd[((size_t)g * 32 + tid) * 3 + 0] = p[pi * 3 + 0] - cx;
        g_nbhd[((size_t)g * 32 + tid) * 3 + 1] = p[pi * 3 + 1] - cy;
        g_nbhd[((size_t)g * 32 + tid) * 3 + 2] = p[pi * 3 + 2] - cz;
    }
}

// ===================== weight prep: transpose + tf32 round =====================
__global__ void wprep_kernel(const float* __restrict__ W2, const float* __restrict__ W3,
                             const float* __restrict__ W4) {
    const int k = blockIdx.x;      // 0..511
    const int tid = threadIdx.x;   // 256
    for (int n = tid; n < 512; n += 256)
        g_W3T[(size_t)n * 512 + k] = tf32_rna(W3[(size_t)k * 512 + n]);
    for (int n = tid; n < 384; n += 256)
        g_W4T[(size_t)n * 512 + k] = tf32_rna(W4[(size_t)k * 384 + n]);
    if (k < 128) {
        for (int n = tid; n < 256; n += 256)
            g_W2T[(size_t)n * 128 + k] = tf32_rna(W2[(size_t)k * 256 + n]);
    }
}

// ===================== E1 via tensor cores =====================
#define LDPA 132
#define E1_SMEM ((128 * LDPA + 2 * TILE + 384 + 5 * 128) * 4)
__global__ void __launch_bounds__(256, 2) e1_tc(
    const float* __restrict__ W1, const float* __restrict__ b1,
    const float* __restrict__ g1, const float* __restrict__ be1,
    const float* __restrict__ m1, const float* __restrict__ v1,
    const float* __restrict__ b2) {
    extern __shared__ __align__(16) float sm[];
    float* As = sm;                       // [128][LDPA] f1 tf32
    float* Bs = sm + 128 * LDPA;          // [2][TILE]
    float* nbs = Bs + 2 * TILE;           // 384
    float* wxs = nbs + 384;               // 128
    float* wys = wxs + 128;
    float* wzs = wys + 128;
    float* scs = wzs + 128;
    float* bbs = scs + 128;
    const uint32_t BsU = smem_u32(Bs);

    const int tid = threadIdx.x;
    const int wid = tid >> 5, lane = tid & 31;
    const int gid = lane >> 2, tig = lane & 3;
    const int wm = (wid >> 1) * 32, wn = (wid & 1) * 64;
    const size_t row0 = (size_t)blockIdx.x * 128;
    const int n0 = blockIdx.y * 128;

#pragma unroll
    for (int s = 0; s < 2; s++) {
#pragma unroll
        for (int it = 0; it < 4; it++) {
            int idx = tid + it * 256;
            int r = idx >> 3, q = idx & 7;
            CP_ASYNC16(BsU + (uint32_t)(s * TILE + r * LDP + q * 4) * 4,
                       &g_W2T[(size_t)(n0 + r) * 128 + s * 32 + q * 4]);
        }
        CP_COMMIT();
    }

    if (tid < 128) {
        int c = tid;
        wxs[c] = W1[c]; wys[c] = W1[128 + c]; wzs[c] = W1[256 + c];
        float sc = g1[c] * rsqrtf(v1[c] + EPSF);
        scs[c] = sc;
        bbs[c] = (b1[c] - m1[c]) * sc + be1[c];
    }
    for (int i = tid; i < 384; i += 256) nbs[i] = g_nbhd[row0 * 3 + i];
    __syncthreads();

    for (int idx = tid; idx < 16384; idx += 256) {
        int c = idx & 127, r = idx >> 7;
        float dot = fmaf(nbs[r * 3 + 2], wzs[c],
                    fmaf(nbs[r * 3 + 1], wys[c],
                         nbs[r * 3 + 0] * wxs[c]));
        float val = fmaf(dot, scs[c], bbs[c]);
        As[r * LDPA + c] = tf32_rna(fmaxf(val, 0.0f));
    }

    float acc[2][8][4];
#pragma unroll
    for (int m = 0; m < 2; m++)
#pragma unroll
        for (int n = 0; n < 8; n++)
#pragma unroll
            for (int q = 0; q < 4; q++) acc[m][n][q] = 0.0f;

    const uint32_t* uh = (const uint32_t*)As;
    for (int kt = 0; kt < 4; kt++) {
        if (kt < 3) { CP_WAIT(1); } else { CP_WAIT(0); }
        __syncthreads();
        const uint32_t* ub = (const uint32_t*)(Bs + (kt & 1) * TILE);
#pragma unroll
        for (int ks = 0; ks < 4; ks++) {
            const int kbA = kt * 32 + ks * 8;
            const int kbB = ks * 8;
            uint32_t ah[2][4], bf[8][2];
#pragma unroll
            for (int m = 0; m < 2; m++) {
                int rb = (wm + m * 16 + gid) * LDPA + kbA + tig;
                ah[m][0] = uh[rb];       ah[m][1] = uh[rb + 8 * LDPA];
                ah[m][2] = uh[rb + 4];   ah[m][3] = uh[rb + 8 * LDPA + 4];
            }
#pragma unroll
            for (int n = 0; n < 8; n++) {
                int nb = (wn + n * 8 + gid) * LDP + kbB + tig;
                bf[n][0] = ub[nb];
                bf[n][1] = ub[nb + 4];
            }
#pragma unroll
            for (int m = 0; m < 2; m++)
#pragma unroll
                for (int n = 0; n < 8; n++) mma16n8k8(acc[m][n], ah[m], bf[n]);
        }
        __syncthreads();
        if (kt + 2 < 4) {
            int s = kt & 1;
#pragma unroll
            for (int it = 0; it < 4; it++) {
                int idx = tid + it * 256;
                int r = idx >> 3, q = idx & 7;
                CP_ASYNC16(BsU + (uint32_t)(s * TILE + r * LDP + q * 4) * 4,
                           &g_W2T[(size_t)(n0 + r) * 128 + (kt + 2) * 32 + q * 4]);
            }
            CP_COMMIT();
        }
    }

    const int g = blockIdx.x * 4 + (wid >> 1);
#pragma unroll
    for (int n = 0; n < 8; n++) {
        int c0 = wn + n * 8 + 2 * tig;
        float bb0 = b2[n0 + c0], bb1 = b2[n0 + c0 + 1];
#pragma unroll
        for (int m = 0; m < 2; m++) {
            size_t r = row0 + wm + m * 16 + gid;
            g_F2[r * 256 + n0 + c0] = tf32_rna(acc[m][n][0] + bb0);
            g_F2[r * 256 + n0 + c0 + 1] = tf32_rna(acc[m][n][1] + bb1);
            g_F2[(r + 8) * 256 + n0 + c0] = tf32_rna(acc[m][n][2] + bb0);
            g_F2[(r + 8) * 256 + n0 + c0 + 1] = tf32_rna(acc[m][n][3] + bb1);
        }
        float v0 = fmaxf(fmaxf(acc[0][n][0], acc[0][n][2]),
                         fmaxf(acc[1][n][0], acc[1][n][2]));
        float v1 = fmaxf(fmaxf(acc[0][n][1], acc[0][n][3]),
                         fmaxf(acc[1][n][1], acc[1][n][3]));
#pragma unroll
        for (int off = 4; off < 32; off <<= 1) {
            v0 = fmaxf(v0, __shfl_xor_sync(0xffffffffu, v0, off));
            v1 = fmaxf(v1, __shfl_xor_sync(0xffffffffu, v1, off));
        }
        if (gid == 0) {
            g_FG[(size_t)g * 256 + n0 + c0] = tf32_rna(v0 + bb0);
            g_FG[(size_t)g * 256 + n0 + c0 + 1] = tf32_rna(v1 + bb1);
        }
    }
}

// ===================== generic single-pass tf32 GEMM (cp.async dbl-buffered) =====================
#define GEMM_SMEM_BASE (4 * TILE * 4)
#define GEMM_SMEM_M1 (GEMM_SMEM_BASE + (512 + 256) * 4)

template <int KTOT, int MODE>
__global__ void __launch_bounds__(256, 2) mma_gemm(
    const float* __restrict__ p0, const float* __restrict__ p1,
    const float* __restrict__ p2, const float* __restrict__ p3,
    const float* __restrict__ p4, float* __restrict__ outp) {
    extern __shared__ __align__(16) float sm[];
    float* As = sm;                 // [2][TILE]
    float* Bs = sm + 2 * TILE;      // [2][TILE]
    const uint32_t AsU = smem_u32(As);
    const uint32_t BsU = smem_u32(Bs);

    const int tid = threadIdx.x;
    const int wid = tid >> 5, lane = tid & 31;
    const int gid = lane >> 2, tig = lane & 3;
    const int wm = (wid >> 1) * 32, wn = (wid & 1) * 64;
    const size_t row0 = (size_t)blockIdx.x * 128;
    const int n0 = blockIdx.y * 128;

    const float* A;
    const float* B;
    int lda;
    if (MODE == 0) { A = g_FG; lda = 256; B = g_W3T; }
    else if (MODE == 1) { A = g_F2; lda = 256; B = g_W3T + 256; }
    else { A = g_F3; lda = 512; B = g_W4T; }

    float* Hs = sm + 4 * TILE;      // MODE1: [4][128]
    float* scs = Hs + 512;
    float* bbs = scs + 128;
    if (MODE == 1) {
        for (int i = tid; i < 512; i += 256)
            Hs[i] = g_Htop[((size_t)blockIdx.x * 4 + (i >> 7)) * 512 + n0 + (i & 127)];
        for (int c = tid; c < 128; c += 256) {
            int gc = n0 + c;
            float sc = p1[gc] * rsqrtf(p4[gc] + EPSF);
            scs[c] = sc;
            bbs[c] = p2[gc] + (p0[gc] - p3[gc]) * sc;
        }
    }

    const int NKT = KTOT / 32;
#pragma unroll
    for (int s = 0; s < 2; s++) {
#pragma unroll
        for (int it = 0; it < 4; it++) {
            int idx = tid + it * 256;
            int r = idx >> 3, q = idx & 7;
            CP_ASYNC16(AsU + (uint32_t)(s * TILE + r * LDP + q * 4) * 4,
                       &A[(row0 + r) * lda + s * 32 + q * 4]);
            CP_ASYNC16(BsU + (uint32_t)(s * TILE + r * LDP + q * 4) * 4,
                       &B[(size_t)(n0 + r) * 512 + s * 32 + q * 4]);
        }
        CP_COMMIT();
    }

    float acc[2][8][4];
#pragma unroll
    for (int m = 0; m < 2; m++)
#pragma unroll
        for (int n = 0; n < 8; n++)
#pragma unroll
            for (int q = 0; q < 4; q++) acc[m][n][q] = 0.0f;

    for (int kt = 0; kt < NKT; kt++) {
        if (kt < NKT - 1) { CP_WAIT(1); } else { CP_WAIT(0); }
        __syncthreads();
        const uint32_t* uh = (const uint32_t*)(As + (kt & 1) * TILE);
        const uint32_t* ub = (const uint32_t*)(Bs + (kt & 1) * TILE);
#pragma unroll
        for (int ks = 0; ks < 4; ks++) {
            const int kb = ks * 8;
            uint32_t ah[2][4], bf[8][2];
#pragma unroll
            for (int m = 0; m < 2; m++) {
                int rb = (wm + m * 16 + gid) * LDP + kb + tig;
                ah[m][0] = uh[rb];       ah[m][1] = uh[rb + 8 * LDP];
                ah[m][2] = uh[rb + 4];   ah[m][3] = uh[rb + 8 * LDP + 4];
            }
#pragma unroll
            for (int n = 0; n < 8; n++) {
                int nb = (wn + n * 8 + gid) * LDP + kb + tig;
                bf[n][0] = ub[nb];
                bf[n][1] = ub[nb + 4];
            }
#pragma unroll
            for (int m = 0; m < 2; m++)
#pragma unroll
                for (int n = 0; n < 8; n++) mma16n8k8(acc[m][n], ah[m], bf[n]);
        }
        __syncthreads();
        if (kt + 2 < NKT) {
            int s = kt & 1;
            int kc0 = (kt + 2) * 32;
#pragma unroll
            for (int it = 0; it < 4; it++) {
                int idx = tid + it * 256;
                int r = idx >> 3, q = idx & 7;
                CP_ASYNC16(AsU + (uint32_t)(s * TILE + r * LDP + q * 4) * 4,
                           &A[(row0 + r) * lda + kc0 + q * 4]);
                CP_ASYNC16(BsU + (uint32_t)(s * TILE + r * LDP + q * 4) * 4,
                           &B[(size_t)(n0 + r) * 512 + kc0 + q * 4]);
            }
            CP_COMMIT();
        }
    }

    if (MODE == 0) {
#pragma unroll
        for (int m = 0; m < 2; m++)
#pragma unroll
            for (int n = 0; n < 8; n++) {
                size_t r = row0 + wm + m * 16 + gid;
                int c = n0 + wn + n * 8 + 2 * tig;
                float2 lo = {acc[m][n][0], acc[m][n][1]};
                float2 hi = {acc[m][n][2], acc[m][n][3]};
                *(float2*)&g_Htop[r * 512 + c] = lo;
                *(float2*)&g_Htop[(r + 8) * 512 + c] = hi;
            }
    } else if (MODE == 1) {
        const int gi = wid >> 1;
#pragma unroll
        for (int m = 0; m < 2; m++)
#pragma unroll
            for (int n = 0; n < 8; n++) {
                int cl = wn + n * 8 + 2 * tig;
                float s0 = scs[cl], s1 = scs[cl + 1];
                float bb0 = bbs[cl], bb1 = bbs[cl + 1];
                float h0 = Hs[gi * 128 + cl], h1 = Hs[gi * 128 + cl + 1];
                size_t r = row0 + wm + m * 16 + gid;
                float2 lo, hi;
                lo.x = tf32_rna(fmaxf(fmaf(acc[m][n][0] + h0, s0, bb0), 0.0f));
                lo.y = tf32_rna(fmaxf(fmaf(acc[m][n][1] + h1, s1, bb1), 0.0f));
                hi.x = tf32_rna(fmaxf(fmaf(acc[m][n][2] + h0, s0, bb0), 0.0f));
                hi.y = tf32_rna(fmaxf(fmaf(acc[m][n][3] + h1, s1, bb1), 0.0f));
                *(float2*)&g_F3[r * 512 + n0 + cl] = lo;
                *(float2*)&g_F3[(r + 8) * 512 + n0 + cl] = hi;
            }
    } else {
        const int g = blockIdx.x * 4 + (wid >> 1);
#pragma unroll
        for (int n = 0; n < 8; n++) {
            float v0 = fmaxf(fmaxf(acc[0][n][0], acc[0][n][2]),
                             fmaxf(acc[1][n][0], acc[1][n][2]));
            float v1 = fmaxf(fmaxf(acc[0][n][1], acc[0][n][3]),
                             fmaxf(acc[1][n][1], acc[1][n][3]));
#pragma unroll
            for (int off = 4; off < 32; off <<= 1) {
                v0 = fmaxf(v0, __shfl_xor_sync(0xffffffffu, v0, off));
                v1 = fmaxf(v1, __shfl_xor_sync(0xffffffffu, v1, off));
            }
            if (gid == 0) {
                int c = n0 + wn + n * 8 + 2 * tig;
                outp[(size_t)g * 384 + c] = v0 + p0[c];
                outp[(size_t)g * 384 + c + 1] = v1 + p0[c + 1];
            }
        }
    }
}

// ===================== pos embed + cls =====================
__global__ void pos_kernel(const float* __restrict__ Wp1, const float* __restrict__ bp1,
                           const float* __restrict__ Wp2, const float* __restrict__ bp2,
                           const float* __restrict__ cls_pos, float* __restrict__ out) {
    const int row = blockIdx.x;
    const int b = blockIdx.y;
    const int tid = threadIdx.x;
    float* op = out + (size_t)NB * NG * ENC + ((size_t)b * (NG + 1) + row) * ENC;
    if (row == 0) {
        for (int c = tid; c < ENC; c += 128) op[c] = cls_pos[c];
        return;
    }
    const int g = b * NG + row - 1;
    float cx = g_centers[g * 3 + 0], cy = g_centers[g * 3 + 1], cz = g_centers[g * 3 + 2];
    __shared__ float h[128];
    {
        float pre = fmaf(cz, Wp1[256 + tid], fmaf(cy, Wp1[128 + tid], fmaf(cx, Wp1[tid], bp1[tid])));
        float x3 = pre * pre * pre;
        float inner = 0.7978845608028654f * fmaf(0.044715f, x3, pre);
        h[tid] = 0.5f * pre * (1.0f + tanhf(inner));
    }
    __syncthreads();
#pragma unroll
    for (int j = 0; j < 3; j++) {
        int c = tid + 128 * j;
        float a = bp2[c];
        for (int k = 0; k < 128; k++) a = fmaf(h[k], Wp2[k * 384 + c], a);
        op[c] = a;
    }
}

// ============================ launch ============================
extern "C" void kernel_launch(void* const* d_in, const int* in_sizes, int n_in,
                              void* d_out, int out_size) {
    const float* pts = (const float*)d_in[0];
    const float* W1 = (const float*)d_in[1];
    const float* b1 = (const float*)d_in[2];
    const float* g1 = (const float*)d_in[3];
    const float* be1 = (const float*)d_in[4];
    const float* m1 = (const float*)d_in[5];
    const float* v1 = (const float*)d_in[6];
    const float* W2 = (const float*)d_in[7];
    const float* b2 = (const float*)d_in[8];
    const float* W3 = (const float*)d_in[9];
    const float* b3 = (const float*)d_in[10];
    const float* g2 = (const float*)d_in[11];
    const float* be2 = (const float*)d_in[12];
    const float* m2 = (const float*)d_in[13];
    const float* v2 = (const float*)d_in[14];
    const float* W4 = (const float*)d_in[15];
    const float* b4 = (const float*)d_in[16];
    const float* Wp1 = (const float*)d_in[17];
    const float* bp1 = (const float*)d_in[18];
    const float* Wp2 = (const float*)d_in[19];
    const float* bp2 = (const float*)d_in[20];
    const float* cls_pos = (const float*)d_in[21];
    float* out = (float*)d_out;

    cudaFuncSetAttribute(fps_kernel, cudaFuncAttributeMaxDynamicSharedMemorySize, FPS_SMEM);
    cudaFuncSetAttribute(e1_tc, cudaFuncAttributeMaxDynamicSharedMemorySize, E1_SMEM);
    cudaFuncSetAttribute(mma_gemm<256, 0>, cudaFuncAttributeMaxDynamicSharedMemorySize, GEMM_SMEM_BASE);
    cudaFuncSetAttribute(mma_gemm<256, 1>, cudaFuncAttributeMaxDynamicSharedMemorySize, GEMM_SMEM_M1);
    cudaFuncSetAttribute(mma_gemm<512, 2>, cudaFuncAttributeMaxDynamicSharedMemorySize, GEMM_SMEM_BASE);

    fps_kernel<<<NB, 512, FPS_SMEM>>>(pts);
    knn_kernel<<<NB * NG, 256>>>(pts);
    wprep_kernel<<<512, 256>>>(W2, W3, W4);
    e1_tc<<<dim3(2048, 2), 256, E1_SMEM>>>(W1, b1, g1, be1, m1, v1, b2);
    mma_gemm<256, 0><<<dim3(64, 4), 256, GEMM_SMEM_BASE>>>(
        nullptr, nullptr, nullptr, nullptr, nullptr, nullptr);
    mma_gemm<256, 1><<<dim3(2048, 4), 256, GEMM_SMEM_M1>>>(
        b3, g2, be2, m2, v2, nullptr);
    mma_gemm<512, 2><<<dim3(2048, 3), 256, GEMM_SMEM_BASE>>>(
        b4, nullptr, nullptr, nullptr, nullptr, out);
    pos_kernel<<<dim3(NG + 1, NB), 128>>>(Wp1, bp1, Wp2, bp2, cls_pos, out);
}

// round 9
// speedup vs baseline: 3.5667x; 1.0004x over previous
#include <cuda_runtime.h>
#include <math.h>
#include <stdint.h>

#define NB 16
#define NP 8192
#define NG 512
#define NM 32
#define ENC 384
#define EPSF 1e-5f

// ---------------- scratch ----------------
__device__ float g_centers[NB * NG * 3];
__device__ float g_nbhd[NB * NG * NM * 3];
__device__ float g_F2[(size_t)NB * NG * NM * 256];   // tf32-rounded
__device__ float g_FG[NB * NG * 256];                // tf32-rounded
__device__ float g_Htop[NB * NG * 512];              // fp32
__device__ float g_F3[(size_t)NB * NG * NM * 512];   // tf32-rounded
__device__ float g_W2T[256 * 128];                   // W2^T tf32
__device__ float g_W3T[512 * 512];                   // W3^T tf32
__device__ float g_W4T[384 * 512];                   // W4^T tf32

__device__ __forceinline__ float tf32_rna(float x) {
    uint32_t u;
    asm("cvt.rna.tf32.f32 %0, %1;" : "=r"(u) : "f"(x));
    return __uint_as_float(u);
}
__device__ __forceinline__ uint32_t smem_u32(const void* p) {
    uint32_t a;
    asm("{ .reg .u64 t; cvta.to.shared.u64 t, %1; cvt.u32.u64 %0, t; }" : "=r"(a) : "l"(p));
    return a;
}
__device__ __forceinline__ void mma16n8k8(float* c, const uint32_t* a, const uint32_t* b) {
    asm volatile(
        "mma.sync.aligned.m16n8k8.row.col.f32.tf32.tf32.f32 "
        "{%0,%1,%2,%3}, {%4,%5,%6,%7}, {%8,%9}, {%0,%1,%2,%3};"
        : "+f"(c[0]), "+f"(c[1]), "+f"(c[2]), "+f"(c[3])
        : "r"(a[0]), "r"(a[1]), "r"(a[2]), "r"(a[3]), "r"(b[0]), "r"(b[1]));
}
#define CP_ASYNC16(dst_u32, src) \
    asm volatile("cp.async.cg.shared.global [%0], [%1], 16;" :: "r"(dst_u32), "l"(src))
#define CP_COMMIT() asm volatile("cp.async.commit_group;" ::: "memory")
#define CP_WAIT(n) asm volatile("cp.async.wait_group %0;" :: "n"(n) : "memory")

#define LDP 36
#define TILE (128 * LDP)

// ============================ FPS =============================
#define FPS_SMEM (3 * NP * 4)
__global__ void __launch_bounds__(512, 1) fps_kernel(const float* __restrict__ pts) {
    extern __shared__ float fsm[];
    float* spx = fsm;
    float* spy = fsm + NP;
    float* spz = fsm + 2 * NP;

    const int b = blockIdx.x;
    const float* p = pts + (size_t)b * NP * 3;
    const int tid = threadIdx.x;
    const int lane = tid & 31, wid = tid >> 5;

    float px[16], py[16], pz[16], dd[16];
#pragma unroll
    for (int i = 0; i < 16; i++) {
        int idx = tid + i * 512;
        float x = p[idx * 3 + 0], y = p[idx * 3 + 1], z = p[idx * 3 + 2];
        px[i] = x; py[i] = y; pz[i] = z; dd[i] = 1e10f;
        spx[idx] = x; spy[idx] = y; spz[idx] = z;
    }
    __shared__ int sFar;
    __shared__ float swv[16];
    __shared__ int swi[16];
    if (tid == 0) sFar = 0;
    __syncthreads();

    for (int s = 0; s < NG; s++) {
        const int far = sFar;
        const float cx = spx[far], cy = spy[far], cz = spz[far];
        if (tid == 0) {
            g_centers[(b * NG + s) * 3 + 0] = cx;
            g_centers[(b * NG + s) * 3 + 1] = cy;
            g_centers[(b * NG + s) * 3 + 2] = cz;
        }
        float bv = -1.0f;
        int bi = 0;
#pragma unroll
        for (int i = 0; i < 16; i++) {
            float dx = __fsub_rn(px[i], cx);
            float dy = __fsub_rn(py[i], cy);
            float dz = __fsub_rn(pz[i], cz);
            float d = __fadd_rn(__fadd_rn(__fmul_rn(dx, dx), __fmul_rn(dy, dy)),
                                __fmul_rn(dz, dz));
            dd[i] = fminf(dd[i], d);
            if (dd[i] > bv) { bv = dd[i]; bi = tid + i * 512; }
        }
#pragma unroll
        for (int off = 16; off > 0; off >>= 1) {
            float ov = __shfl_xor_sync(0xffffffffu, bv, off);
            int oi = __shfl_xor_sync(0xffffffffu, bi, off);
            if (ov > bv || (ov == bv && oi < bi)) { bv = ov; bi = oi; }
        }
        if (lane == 0) { swv[wid] = bv; swi[wid] = bi; }
        __syncthreads();
        if (wid == 0) {
            float v = (lane < 16) ? swv[lane] : -2.0f;
            int ii = (lane < 16) ? swi[lane] : 0x7fffffff;
#pragma unroll
            for (int off = 8; off > 0; off >>= 1) {
                float ov = __shfl_xor_sync(0xffffffffu, v, off);
                int oi = __shfl_xor_sync(0xffffffffu, ii, off);
                if (ov > v || (ov == v && oi < ii)) { v = ov; ii = oi; }
            }
            if (lane == 0) sFar = ii;
        }
        __syncthreads();
    }
}

// ============================ kNN (exact radix-select) =============================
// Set semantics: downstream consumers only max-pool over the neighborhood, so
// output order is irrelevant. Selection set matches top_k exactly:
// all d < T plus smallest-index ties d == T, T = exact 32nd-smallest distance.
__global__ void __launch_bounds__(256, 4) knn_kernel(const float* __restrict__ pts) {
    const int g = blockIdx.x;
    const int b = g >> 9;
    const float* p = pts + (size_t)b * NP * 3;
    const int tid = threadIdx.x;
    const int wid = tid >> 5;

    const float cx = g_centers[g * 3 + 0];
    const float cy = g_centers[g * 3 + 1];
    const float cz = g_centers[g * 3 + 2];

    uint32_t key[32];
#pragma unroll
    for (int j = 0; j < 32; j++) {
        int idx = tid + j * 256;
        float dx = __fsub_rn(cx, p[idx * 3 + 0]);
        float dy = __fsub_rn(cy, p[idx * 3 + 1]);
        float dz = __fsub_rn(cz, p[idx * 3 + 2]);
        float d = __fadd_rn(__fadd_rn(__fmul_rn(dx, dx), __fmul_rn(dy, dy)),
                            __fmul_rn(dz, dz));
        key[j] = __float_as_uint(d);   // d >= 0: uint order == float order
    }

    __shared__ uint32_t hist[8][256];
    __shared__ uint32_t cum_bin, cum_r;
    __shared__ int c_less, c_tie;
    __shared__ int sel[32];
    __shared__ int ties[128];

    uint32_t prefix = 0;
    uint32_t r = 32;    // 1-based rank of target (32nd smallest)

#pragma unroll 1
    for (int pass = 0; pass < 4; pass++) {
        const int shift = 24 - pass * 8;
        for (int i = tid; i < 8 * 256; i += 256) (&hist[0][0])[i] = 0;
        __syncthreads();
        const uint32_t pmask = (pass == 0) ? 0u : (0xFFFFFFFFu << (shift + 8));
#pragma unroll
        for (int j = 0; j < 32; j++) {
            if ((key[j] & pmask) == prefix)
                atomicAdd(&hist[wid][(key[j] >> shift) & 255u], 1u);
        }
        __syncthreads();
        if (wid == 0) {
            const int lane = tid & 31;
            uint32_t binc[8];
            uint32_t lsum = 0;
#pragma unroll
            for (int q = 0; q < 8; q++) {
                uint32_t s = 0;
#pragma unroll
                for (int w = 0; w < 8; w++) s += hist[w][lane * 8 + q];
                binc[q] = s;
                lsum += s;
            }
            uint32_t inc = lsum;
#pragma unroll
            for (int off = 1; off < 32; off <<= 1) {
                uint32_t v = __shfl_up_sync(0xffffffffu, inc, off);
                if (lane >= off) inc += v;
            }
            uint32_t excl = inc - lsum;
            uint32_t vote = __ballot_sync(0xffffffffu, inc >= r);
            int selLane = __ffs(vote) - 1;
            if (lane == selLane) {
                uint32_t rr = r - excl;   // 1-based within this lane's 8 bins
                uint32_t c = 0;
                int bq = 0;
#pragma unroll
                for (int q = 0; q < 8; q++) {
                    if (c + binc[q] >= rr) { bq = q; break; }
                    c += binc[q];
                }
                cum_bin = (uint32_t)(lane * 8 + bq);
                cum_r = rr - c;
            }
        }
        __syncthreads();
        prefix |= (cum_bin << shift);
        r = cum_r;
        __syncthreads();
    }
    const uint32_t T = prefix;

    if (tid == 0) { c_less = 0; c_tie = 0; }
    __syncthreads();
#pragma unroll
    for (int j = 0; j < 32; j++) {
        int pidx = tid + j * 256;
        if (key[j] < T) {
            int pos = atomicAdd(&c_less, 1);
            sel[pos] = pidx;                      // < 32 guaranteed
        } else if (key[j] == T) {
            int pos = atomicAdd(&c_tie, 1);
            if (pos < 128) ties[pos] = pidx;
        }
    }
    __syncthreads();
    if (tid == 0) {
        int need = 32 - c_less;
        int m = c_tie < 128 ? c_tie : 128;
        for (int t = 0; t < need; t++) {
            int best = 0x7fffffff, bj = 0;
            for (int j2 = 0; j2 < m; j2++)
                if (ties[j2] < best) { best = ties[j2]; bj = j2; }
            sel[c_less + t] = best;
            ties[bj] = 0x7fffffff;
        }
    }
    __syncthreads();
    if (tid < 32) {
        int pi = sel[tid];
        g_nbhd[((size_t)g * 32 + tid) * 3 + 0] = p[pi * 3 + 0] - cx;
        g_nbhd[((size_t)g * 32 + tid) * 3 + 1] = p[pi * 3 + 1] - cy;
        g_nbhd[((size_t)g * 32 + tid) * 3 + 2] = p[pi * 3 + 2] - cz;
    }
}

// ===================== weight prep: transpose + tf32 round =====================
__global__ void wprep_kernel(const float* __restrict__ W2, const float* __restrict__ W3,
                             const float* __restrict__ W4) {
    const int k = blockIdx.x;      // 0..511
    const int tid = threadIdx.x;   // 256
    for (int n = tid; n < 512; n += 256)
        g_W3T[(size_t)n * 512 + k] = tf32_rna(W3[(size_t)k * 512 + n]);
    for (int n = tid; n < 384; n += 256)
        g_W4T[(size_t)n * 512 + k] = tf32_rna(W4[(size_t)k * 384 + n]);
    if (k < 128) {
        for (int n = tid; n < 256; n += 256)
            g_W2T[(size_t)n * 128 + k] = tf32_rna(W2[(size_t)k * 256 + n]);
    }
}

// ===================== E1 via tensor cores =====================
#define LDPA 132
#define E1_SMEM ((128 * LDPA + 2 * TILE + 384 + 5 * 128) * 4)
__global__ void __launch_bounds__(256, 2) e1_tc(
    const float* __restrict__ W1, const float* __restrict__ b1,
    const float* __restrict__ g1, const float* __restrict__ be1,
    const float* __restrict__ m1, const float* __restrict__ v1,
    const float* __restrict__ b2) {
    extern __shared__ __align__(16) float sm[];
    float* As = sm;                       // [128][LDPA] f1 tf32
    float* Bs = sm + 128 * LDPA;          // [2][TILE]
    float* nbs = Bs + 2 * TILE;           // 384
    float* wxs = nbs + 384;               // 128
    float* wys = wxs + 128;
    float* wzs = wys + 128;
    float* scs = wzs + 128;
    float* bbs = scs + 128;
    const uint32_t BsU = smem_u32(Bs);

    const int tid = threadIdx.x;
    const int wid = tid >> 5, lane = tid & 31;
    const int gid = lane >> 2, tig = lane & 3;
    const int wm = (wid >> 1) * 32, wn = (wid & 1) * 64;
    const size_t row0 = (size_t)blockIdx.x * 128;
    const int n0 = blockIdx.y * 128;

#pragma unroll
    for (int s = 0; s < 2; s++) {
#pragma unroll
        for (int it = 0; it < 4; it++) {
            int idx = tid + it * 256;
            int r = idx >> 3, q = idx & 7;
            CP_ASYNC16(BsU + (uint32_t)(s * TILE + r * LDP + q * 4) * 4,
                       &g_W2T[(size_t)(n0 + r) * 128 + s * 32 + q * 4]);
        }
        CP_COMMIT();
    }

    if (tid < 128) {
        int c = tid;
        wxs[c] = W1[c]; wys[c] = W1[128 + c]; wzs[c] = W1[256 + c];
        float sc = g1[c] * rsqrtf(v1[c] + EPSF);
        scs[c] = sc;
        bbs[c] = (b1[c] - m1[c]) * sc + be1[c];
    }
    for (int i = tid; i < 384; i += 256) nbs[i] = g_nbhd[row0 * 3 + i];
    __syncthreads();

    for (int idx = tid; idx < 16384; idx += 256) {
        int c = idx & 127, r = idx >> 7;
        float dot = fmaf(nbs[r * 3 + 2], wzs[c],
                    fmaf(nbs[r * 3 + 1], wys[c],
                         nbs[r * 3 + 0] * wxs[c]));
        float val = fmaf(dot, scs[c], bbs[c]);
        As[r * LDPA + c] = tf32_rna(fmaxf(val, 0.0f));
    }

    float acc[2][8][4];
#pragma unroll
    for (int m = 0; m < 2; m++)
#pragma unroll
        for (int n = 0; n < 8; n++)
#pragma unroll
            for (int q = 0; q < 4; q++) acc[m][n][q] = 0.0f;

    const uint32_t* uh = (const uint32_t*)As;
    for (int kt = 0; kt < 4; kt++) {
        if (kt < 3) { CP_WAIT(1); } else { CP_WAIT(0); }
        __syncthreads();
        const uint32_t* ub = (const uint32_t*)(Bs + (kt & 1) * TILE);
#pragma unroll
        for (int ks = 0; ks < 4; ks++) {
            const int kbA = kt * 32 + ks * 8;
            const int kbB = ks * 8;
            uint32_t ah[2][4], bf[8][2];
#pragma unroll
            for (int m = 0; m < 2; m++) {
                int rb = (wm + m * 16 + gid) * LDPA + kbA + tig;
                ah[m][0] = uh[rb];       ah[m][1] = uh[rb + 8 * LDPA];
                ah[m][2] = uh[rb + 4];   ah[m][3] = uh[rb + 8 * LDPA + 4];
            }
#pragma unroll
            for (int n = 0; n < 8; n++) {
                int nb = (wn + n * 8 + gid) * LDP + kbB + tig;
                bf[n][0] = ub[nb];
                bf[n][1] = ub[nb + 4];
            }
#pragma unroll
            for (int m = 0; m < 2; m++)
#pragma unroll
                for (int n = 0; n < 8; n++) mma16n8k8(acc[m][n], ah[m], bf[n]);
        }
        __syncthreads();
        if (kt + 2 < 4) {
            int s = kt & 1;
#pragma unroll
            for (int it = 0; it < 4; it++) {
                int idx = tid + it * 256;
                int r = idx >> 3, q = idx & 7;
                CP_ASYNC16(BsU + (uint32_t)(s * TILE + r * LDP + q * 4) * 4,
                           &g_W2T[(size_t)(n0 + r) * 128 + (kt + 2) * 32 + q * 4]);
            }
            CP_COMMIT();
        }
    }

    const int g = blockIdx.x * 4 + (wid >> 1);
#pragma unroll
    for (int n = 0; n < 8; n++) {
        int c0 = wn + n * 8 + 2 * tig;
        float bb0 = b2[n0 + c0], bb1 = b2[n0 + c0 + 1];
#pragma unroll
        for (int m = 0; m < 2; m++) {
            size_t r = row0 + wm + m * 16 + gid;
            g_F2[r * 256 + n0 + c0] = tf32_rna(acc[m][n][0] + bb0);
            g_F2[r * 256 + n0 + c0 + 1] = tf32_rna(acc[m][n][1] + bb1);
            g_F2[(r + 8) * 256 + n0 + c0] = tf32_rna(acc[m][n][2] + bb0);
            g_F2[(r + 8) * 256 + n0 + c0 + 1] = tf32_rna(acc[m][n][3] + bb1);
        }
        float v0 = fmaxf(fmaxf(acc[0][n][0], acc[0][n][2]),
                         fmaxf(acc[1][n][0], acc[1][n][2]));
        float v1 = fmaxf(fmaxf(acc[0][n][1], acc[0][n][3]),
                         fmaxf(acc[1][n][1], acc[1][n][3]));
#pragma unroll
        for (int off = 4; off < 32; off <<= 1) {
            v0 = fmaxf(v0, __shfl_xor_sync(0xffffffffu, v0, off));
            v1 = fmaxf(v1, __shfl_xor_sync(0xffffffffu, v1, off));
        }
        if (gid == 0) {
            g_FG[(size_t)g * 256 + n0 + c0] = tf32_rna(v0 + bb0);
            g_FG[(size_t)g * 256 + n0 + c0 + 1] = tf32_rna(v1 + bb1);
        }
    }
}

// ===================== generic single-pass tf32 GEMM (cp.async dbl-buffered) =====================
#define GEMM_SMEM_BASE (4 * TILE * 4)
#define GEMM_SMEM_M1 (GEMM_SMEM_BASE + (512 + 256) * 4)

template <int KTOT, int MODE>
__global__ void __launch_bounds__(256, 2) mma_gemm(
    const float* __restrict__ p0, const float* __restrict__ p1,
    const float* __restrict__ p2, const float* __restrict__ p3,
    const float* __restrict__ p4, float* __restrict__ outp) {
    extern __shared__ __align__(16) float sm[];
    float* As = sm;                 // [2][TILE]
    float* Bs = sm + 2 * TILE;      // [2][TILE]
    const uint32_t AsU = smem_u32(As);
    const uint32_t BsU = smem_u32(Bs);

    const int tid = threadIdx.x;
    const int wid = tid >> 5, lane = tid & 31;
    const int gid = lane >> 2, tig = lane & 3;
    const int wm = (wid >> 1) * 32, wn = (wid & 1) * 64;
    const size_t row0 = (size_t)blockIdx.x * 128;
    const int n0 = blockIdx.y * 128;

    const float* A;
    const float* B;
    int lda;
    if (MODE == 0) { A = g_FG; lda = 256; B = g_W3T; }
    else if (MODE == 1) { A = g_F2; lda = 256; B = g_W3T + 256; }
    else { A = g_F3; lda = 512; B = g_W4T; }

    float* Hs = sm + 4 * TILE;      // MODE1: [4][128]
    float* scs = Hs + 512;
    float* bbs = scs + 128;
    if (MODE == 1) {
        for (int i = tid; i < 512; i += 256)
            Hs[i] = g_Htop[((size_t)blockIdx.x * 4 + (i >> 7)) * 512 + n0 + (i & 127)];
        for (int c = tid; c < 128; c += 256) {
            int gc = n0 + c;
            float sc = p1[gc] * rsqrtf(p4[gc] + EPSF);
            scs[c] = sc;
            bbs[c] = p2[gc] + (p0[gc] - p3[gc]) * sc;
        }
    }

    const int NKT = KTOT / 32;
#pragma unroll
    for (int s = 0; s < 2; s++) {
#pragma unroll
        for (int it = 0; it < 4; it++) {
            int idx = tid + it * 256;
            int r = idx >> 3, q = idx & 7;
            CP_ASYNC16(AsU + (uint32_t)(s * TILE + r * LDP + q * 4) * 4,
                       &A[(row0 + r) * lda + s * 32 + q * 4]);
            CP_ASYNC16(BsU + (uint32_t)(s * TILE + r * LDP + q * 4) * 4,
                       &B[(size_t)(n0 + r) * 512 + s * 32 + q * 4]);
        }
        CP_COMMIT();
    }

    float acc[2][8][4];
#pragma unroll
    for (int m = 0; m < 2; m++)
#pragma unroll
        for (int n = 0; n < 8; n++)
#pragma unroll
            for (int q = 0; q < 4; q++) acc[m][n][q] = 0.0f;

    for (int kt = 0; kt < NKT; kt++) {
        if (kt < NKT - 1) { CP_WAIT(1); } else { CP_WAIT(0); }
        __syncthreads();
        const uint32_t* uh = (const uint32_t*)(As + (kt & 1) * TILE);
        const uint32_t* ub = (const uint32_t*)(Bs + (kt & 1) * TILE);
#pragma unroll
        for (int ks = 0; ks < 4; ks++) {
            const int kb = ks * 8;
            uint32_t ah[2][4], bf[8][2];
#pragma unroll
            for (int m = 0; m < 2; m++) {
                int rb = (wm + m * 16 + gid) * LDP + kb + tig;
                ah[m][0] = uh[rb];       ah[m][1] = uh[rb + 8 * LDP];
                ah[m][2] = uh[rb + 4];   ah[m][3] = uh[rb + 8 * LDP + 4];
            }
#pragma unroll
            for (int n = 0; n < 8; n++) {
                int nb = (wn + n * 8 + gid) * LDP + kb + tig;
                bf[n][0] = ub[nb];
                bf[n][1] = ub[nb + 4];
            }
#pragma unroll
            for (int m = 0; m < 2; m++)
#pragma unroll
                for (int n = 0; n < 8; n++) mma16n8k8(acc[m][n], ah[m], bf[n]);
        }
        __syncthreads();
        if (kt + 2 < NKT) {
            int s = kt & 1;
            int kc0 = (kt + 2) * 32;
#pragma unroll
            for (int it = 0; it < 4; it++) {
                int idx = tid + it * 256;
                int r = idx >> 3, q = idx & 7;
                CP_ASYNC16(AsU + (uint32_t)(s * TILE + r * LDP + q * 4) * 4,
                           &A[(row0 + r) * lda + kc0 + q * 4]);
                CP_ASYNC16(BsU + (uint32_t)(s * TILE + r * LDP + q * 4) * 4,
                           &B[(size_t)(n0 + r) * 512 + kc0 + q * 4]);
            }
            CP_COMMIT();
        }
    }

    if (MODE == 0) {
#pragma unroll
        for (int m = 0; m < 2; m++)
#pragma unroll
            for (int n = 0; n < 8; n++) {
                size_t r = row0 + wm + m * 16 + gid;
                int c = n0 + wn + n * 8 + 2 * tig;
                float2 lo = {acc[m][n][0], acc[m][n][1]};
                float2 hi = {acc[m][n][2], acc[m][n][3]};
                *(float2*)&g_Htop[r * 512 + c] = lo;
                *(float2*)&g_Htop[(r + 8) * 512 + c] = hi;
            }
    } else if (MODE == 1) {
        const int gi = wid >> 1;
#pragma unroll
        for (int m = 0; m < 2; m++)
#pragma unroll
            for (int n = 0; n < 8; n++) {
                int cl = wn + n * 8 + 2 * tig;
                float s0 = scs[cl], s1 = scs[cl + 1];
                float bb0 = bbs[cl], bb1 = bbs[cl + 1];
                float h0 = Hs[gi * 128 + cl], h1 = Hs[gi * 128 + cl + 1];
                size_t r = row0 + wm + m * 16 + gid;
                float2 lo, hi;
                lo.x = tf32_rna(fmaxf(fmaf(acc[m][n][0] + h0, s0, bb0), 0.0f));
                lo.y = tf32_rna(fmaxf(fmaf(acc[m][n][1] + h1, s1, bb1), 0.0f));
                hi.x = tf32_rna(fmaxf(fmaf(acc[m][n][2] + h0, s0, bb0), 0.0f));
                hi.y = tf32_rna(fmaxf(fmaf(acc[m][n][3] + h1, s1, bb1), 0.0f));
                *(float2*)&g_F3[r * 512 + n0 + cl] = lo;
                *(float2*)&g_F3[(r + 8) * 512 + n0 + cl] = hi;
            }
    } else {
        const int g = blockIdx.x * 4 + (wid >> 1);
#pragma unroll
        for (int n = 0; n < 8; n++) {
            float v0 = fmaxf(fmaxf(acc[0][n][0], acc[0][n][2]),
                             fmaxf(acc[1][n][0], acc[1][n][2]));
            float v1 = fmaxf(fmaxf(acc[0][n][1], acc[0][n][3]),
                             fmaxf(acc[1][n][1], acc[1][n][3]));
#pragma unroll
            for (int off = 4; off < 32; off <<= 1) {
                v0 = fmaxf(v0, __shfl_xor_sync(0xffffffffu, v0, off));
                v1 = fmaxf(v1, __shfl_xor_sync(0xffffffffu, v1, off));
            }
            if (gid == 0) {
                int c = n0 + wn + n * 8 + 2 * tig;
                outp[(size_t)g * 384 + c] = v0 + p0[c];
                outp[(size_t)g * 384 + c + 1] = v1 + p0[c + 1];
            }
        }
    }
}

// ===================== pos embed + cls =====================
__global__ void pos_kernel(const float* __restrict__ Wp1, const float* __restrict__ bp1,
                           const float* __restrict__ Wp2, const float* __restrict__ bp2,
                           const float* __restrict__ cls_pos, float* __restrict__ out) {
    const int row = blockIdx.x;
    const int b = blockIdx.y;
    const int tid = threadIdx.x;
    float* op = out + (size_t)NB * NG * ENC + ((size_t)b * (NG + 1) + row) * ENC;
    if (row == 0) {
        for (int c = tid; c < ENC; c += 128) op[c] = cls_pos[c];
        return;
    }
    const int g = b * NG + row - 1;
    float cx = g_centers[g * 3 + 0], cy = g_centers[g * 3 + 1], cz = g_centers[g * 3 + 2];
    __shared__ float h[128];
    {
        float pre = fmaf(cz, Wp1[256 + tid], fmaf(cy, Wp1[128 + tid], fmaf(cx, Wp1[tid], bp1[tid])));
        float x3 = pre * pre * pre;
        float inner = 0.7978845608028654f * fmaf(0.044715f, x3, pre);
        h[tid] = 0.5f * pre * (1.0f + tanhf(inner));
    }
    __syncthreads();
#pragma unroll
    for (int j = 0; j < 3; j++) {
        int c = tid + 128 * j;
        float a = bp2[c];
        for (int k = 0; k < 128; k++) a = fmaf(h[k], Wp2[k * 384 + c], a);
        op[c] = a;
    }
}

// ============================ launch ============================
extern "C" void kernel_launch(void* const* d_in, const int* in_sizes, int n_in,
                              void* d_out, int out_size) {
    const float* pts = (const float*)d_in[0];
    const float* W1 = (const float*)d_in[1];
    const float* b1 = (const float*)d_in[2];
    const float* g1 = (const float*)d_in[3];
    const float* be1 = (const float*)d_in[4];
    const float* m1 = (const float*)d_in[5];
    const float* v1 = (const float*)d_in[6];
    const float* W2 = (const float*)d_in[7];
    const float* b2 = (const float*)d_in[8];
    const float* W3 = (const float*)d_in[9];
    const float* b3 = (const float*)d_in[10];
    const float* g2 = (const float*)d_in[11];
    const float* be2 = (const float*)d_in[12];
    const float* m2 = (const float*)d_in[13];
    const float* v2 = (const float*)d_in[14];
    const float* W4 = (const float*)d_in[15];
    const float* b4 = (const float*)d_in[16];
    const float* Wp1 = (const float*)d_in[17];
    const float* bp1 = (const float*)d_in[18];
    const float* Wp2 = (const float*)d_in[19];
    const float* bp2 = (const float*)d_in[20];
    const float* cls_pos = (const float*)d_in[21];
    float* out = (float*)d_out;

    cudaFuncSetAttribute(fps_kernel, cudaFuncAttributeMaxDynamicSharedMemorySize, FPS_SMEM);
    cudaFuncSetAttribute(e1_tc, cudaFuncAttributeMaxDynamicSharedMemorySize, E1_SMEM);
    cudaFuncSetAttribute(mma_gemm<256, 0>, cudaFuncAttributeMaxDynamicSharedMemorySize, GEMM_SMEM_BASE);
    cudaFuncSetAttribute(mma_gemm<256, 1>, cudaFuncAttributeMaxDynamicSharedMemorySize, GEMM_SMEM_M1);
    cudaFuncSetAttribute(mma_gemm<512, 2>, cudaFuncAttributeMaxDynamicSharedMemorySize, GEMM_SMEM_BASE);

    fps_kernel<<<NB, 512, FPS_SMEM>>>(pts);
    knn_kernel<<<NB * NG, 256>>>(pts);
    wprep_kernel<<<512, 256>>>(W2, W3, W4);
    e1_tc<<<dim3(2048, 2), 256, E1_SMEM>>>(W1, b1, g1, be1, m1, v1, b2);
    mma_gemm<256, 0><<<dim3(64, 4), 256, GEMM_SMEM_BASE>>>(
        nullptr, nullptr, nullptr, nullptr, nullptr, nullptr);
    mma_gemm<256, 1><<<dim3(2048, 4), 256, GEMM_SMEM_M1>>>(
        b3, g2, be2, m2, v2, nullptr);
    mma_gemm<512, 2><<<dim3(2048, 3), 256, GEMM_SMEM_BASE>>>(
        b4, nullptr, nullptr, nullptr, nullptr, out);
    pos_kernel<<<dim3(NG + 1, NB), 128>>>(Wp1, bp1, Wp2, bp2, cls_pos, out);
}